// round 4
// baseline (speedup 1.0000x reference)
#include <cuda_runtime.h>
#include <cuda_bf16.h>

// Problem constants
#define BATCH  4
#define CH     256
#define IMG    256
#define NGROUP 32
#define CPG    8      // channels per group
#define WSZ    8      // window size
#define NT     64     // tokens per window
#define NHEAD  8
#define DHEAD  32
#define GN_EPS 1e-5f

// GroupNorm stats scratch (device globals: no allocation allowed)
__device__ float g_mean[BATCH * NGROUP];
__device__ float g_rstd[BATCH * NGROUP];

// ---------------------------------------------------------------------------
// Kernel 1: GroupNorm statistics. One block per (b, g).
// Group g covers channels [g*8, g*8+8), contiguous in x's layout, so each
// (b,g) reduces a contiguous chunk of 8*IMG*IMG floats.
// ---------------------------------------------------------------------------
__global__ void gn_stats_kernel(const float* __restrict__ x)
{
    const int bg = blockIdx.x;                       // 0..127
    const float4* p = reinterpret_cast<const float4*>(x + (size_t)bg * CPG * IMG * IMG);
    const int n4 = (CPG * IMG * IMG) / 4;            // 131072

    float s = 0.f, sq = 0.f;
    for (int i = threadIdx.x; i < n4; i += blockDim.x) {
        float4 v = p[i];
        s  += v.x + v.y + v.z + v.w;
        sq += v.x * v.x + v.y * v.y + v.z * v.z + v.w * v.w;
    }
    for (int o = 16; o; o >>= 1) {
        s  += __shfl_down_sync(0xFFFFFFFFu, s,  o);
        sq += __shfl_down_sync(0xFFFFFFFFu, sq, o);
    }
    __shared__ float ss[32], ssq[32];
    const int w = threadIdx.x >> 5, l = threadIdx.x & 31;
    if (l == 0) { ss[w] = s; ssq[w] = sq; }
    __syncthreads();
    if (w == 0) {
        const int nw = blockDim.x >> 5;
        s  = (l < nw) ? ss[l]  : 0.f;
        sq = (l < nw) ? ssq[l] : 0.f;
        for (int o = 16; o; o >>= 1) {
            s  += __shfl_down_sync(0xFFFFFFFFu, s,  o);
            sq += __shfl_down_sync(0xFFFFFFFFu, sq, o);
        }
        if (l == 0) {
            const float invN = 1.f / (float)(CPG * IMG * IMG);
            const float m   = s * invN;
            const float var = sq * invN - m * m;      // biased variance
            g_mean[bg] = m;
            g_rstd[bg] = rsqrtf(var + GN_EPS);
        }
    }
}

// ---------------------------------------------------------------------------
// Kernel 2: fully fused window attention. One block per 8x8 window.
//
// Shared memory layout (floats), total 52224 floats = 208896 bytes:
//   XIN [64][260]  normalized window input (pad 260 -> float4-aligned rows)
//   OF  [64][260]  concatenated per-head attention output
//   WP  [256][33]  staged weight panel, k-major (bank-conflict-free)
//   QS/KS/VS [64][33] per-head Q,K,V (QS reused as out-proj staging)
//   SS  [64][65]   attention scores
// ---------------------------------------------------------------------------
#define XIN_OFF 0
#define OF_OFF  16640
#define WP_OFF  33280
#define QS_OFF  41728
#define KS_OFF  43840
#define VS_OFF  45952
#define SS_OFF  48064
#define SMEM_FLOATS 52224

__global__ void __launch_bounds__(256, 1)
win_attn_kernel(const float* __restrict__ x,
                const float* __restrict__ gnw, const float* __restrict__ gnb,
                const float* __restrict__ Wq,  const float* __restrict__ Wk,
                const float* __restrict__ Wv,  const float* __restrict__ Wo,
                const float* __restrict__ bo,  const float* __restrict__ pos,
                const float* __restrict__ scale,
                float* __restrict__ out)
{
    extern __shared__ float sm[];
    float* XIN = sm + XIN_OFF;
    float* OF  = sm + OF_OFF;
    float* WP  = sm + WP_OFF;
    float* QS  = sm + QS_OFF;
    float* KS  = sm + KS_OFF;
    float* VS  = sm + VS_OFF;
    float* SS  = sm + SS_OFF;

    const int tid = threadIdx.x;
    const int bid = blockIdx.x;               // 4096 windows
    const int b   = bid >> 10;
    const int wh  = (bid >> 5) & 31;
    const int ww  = bid & 31;
    const size_t xbase = (size_t)b * CH * IMG * IMG;
    const int    hw0   = (wh * WSZ) * IMG + ww * WSZ;

    // ---- load window + apply GroupNorm ----
    for (int idx = tid; idx < NT * CH; idx += 256) {
        const int c = idx >> 6;               // channel
        const int t = idx & 63;               // token
        const int off = hw0 + ((t >> 3) * IMG) + (t & 7);
        const float v = x[xbase + (size_t)c * IMG * IMG + off];
        const int g = c >> 3;
        const float xn = (v - g_mean[b * NGROUP + g]) * g_rstd[b * NGROUP + g]
                         * gnw[c] + gnb[c];
        XIN[t * 260 + c] = xn;
    }
    __syncthreads();

    const float qscale = scale[0];
    const int oc      = tid & 31;             // output channel within 32-panel
    const int tokBase = (tid >> 5) * 8;       // 8 tokens per thread

    // Stage a 32-row weight panel (rows [row0,row0+32) of a 256x256 matrix)
    // into WP as k-major [k][oc] with pad 33. Global reads coalesced.
    auto load_panel = [&](const float* __restrict__ Wsrc, int row0) {
        for (int idx = tid; idx < 32 * 256; idx += 256) {
            const int po = idx >> 8;          // panel output channel 0..31
            const int k  = idx & 255;
            WP[k * 33 + po] = Wsrc[(size_t)(row0 + po) * 256 + k];
        }
    };

    // dst[t*33+oc] = mul * sum_k A[t*260+k] * WP[k*33+oc]    (64x32, k=256)
    auto gemm_panel = [&](const float* __restrict__ A, float* __restrict__ dst,
                          float mul) {
        float acc[8];
        #pragma unroll
        for (int i = 0; i < 8; i++) acc[i] = 0.f;
        for (int k = 0; k < 256; k += 4) {
            const float w0 = WP[(k + 0) * 33 + oc];
            const float w1 = WP[(k + 1) * 33 + oc];
            const float w2 = WP[(k + 2) * 33 + oc];
            const float w3 = WP[(k + 3) * 33 + oc];
            #pragma unroll
            for (int i = 0; i < 8; i++) {
                const float4 a = *reinterpret_cast<const float4*>(
                    &A[(tokBase + i) * 260 + k]);
                acc[i] = fmaf(a.x, w0, acc[i]);
                acc[i] = fmaf(a.y, w1, acc[i]);
                acc[i] = fmaf(a.z, w2, acc[i]);
                acc[i] = fmaf(a.w, w3, acc[i]);
            }
        }
        #pragma unroll
        for (int i = 0; i < 8; i++)
            dst[(tokBase + i) * 33 + oc] = acc[i] * mul;
    };

    // ---- per-head attention ----
    for (int h = 0; h < NHEAD; h++) {
        const int r0 = h * DHEAD;

        load_panel(Wq, r0); __syncthreads();
        gemm_panel(XIN, QS, qscale); __syncthreads();

        load_panel(Wk, r0); __syncthreads();
        gemm_panel(XIN, KS, 1.f); __syncthreads();

        load_panel(Wv, r0); __syncthreads();
        gemm_panel(XIN, VS, 1.f); __syncthreads();

        // S = Q K^T + pos_emb[h]   (64x64, k=32). 4x4 register tile/thread.
        {
            const int i0 = (tid >> 4) * 4;
            const int j0 = (tid & 15) * 4;
            float a[16];
            #pragma unroll
            for (int z = 0; z < 16; z++) a[z] = 0.f;
            for (int d = 0; d < DHEAD; d++) {
                float qv[4], kv[4];
                #pragma unroll
                for (int ii = 0; ii < 4; ii++) qv[ii] = QS[(i0 + ii) * 33 + d];
                #pragma unroll
                for (int jj = 0; jj < 4; jj++) kv[jj] = KS[(j0 + jj) * 33 + d];
                #pragma unroll
                for (int ii = 0; ii < 4; ii++)
                    #pragma unroll
                    for (int jj = 0; jj < 4; jj++)
                        a[ii * 4 + jj] = fmaf(qv[ii], kv[jj], a[ii * 4 + jj]);
            }
            #pragma unroll
            for (int ii = 0; ii < 4; ii++)
                #pragma unroll
                for (int jj = 0; jj < 4; jj++)
                    SS[(i0 + ii) * 65 + (j0 + jj)] =
                        a[ii * 4 + jj] + pos[((h * 64) + i0 + ii) * 64 + j0 + jj];
        }
        __syncthreads();

        // row softmax (one row per thread, threads 0..63)
        if (tid < 64) {
            float m = -1e30f;
            for (int j = 0; j < 64; j++) m = fmaxf(m, SS[tid * 65 + j]);
            float s = 0.f;
            for (int j = 0; j < 64; j++) {
                const float e = __expf(SS[tid * 65 + j] - m);
                SS[tid * 65 + j] = e;
                s += e;
            }
            const float inv = 1.f / s;
            for (int j = 0; j < 64; j++) SS[tid * 65 + j] *= inv;
        }
        __syncthreads();

        // O_h = S @ V_h  -> OF[t][h*32+oc]   (64x32, k=64)
        {
            float acc[8];
            #pragma unroll
            for (int i = 0; i < 8; i++) acc[i] = 0.f;
            for (int k = 0; k < 64; k++) {
                const float vv = VS[k * 33 + oc];
                #pragma unroll
                for (int i = 0; i < 8; i++)
                    acc[i] = fmaf(SS[(tokBase + i) * 65 + k], vv, acc[i]);
            }
            #pragma unroll
            for (int i = 0; i < 8; i++)
                OF[(tokBase + i) * 260 + r0 + oc] = acc[i];
        }
        __syncthreads();
    }

    // ---- output projection + bias + residual, 8 panels of 32 channels ----
    for (int cp = 0; cp < 8; cp++) {
        load_panel(Wo, cp * 32); __syncthreads();
        gemm_panel(OF, QS, 1.f);             // stage result in QS
        __syncthreads();
        for (int idx = tid; idx < NT * 32; idx += 256) {
            const int cl = idx >> 6;          // local channel 0..31
            const int t  = idx & 63;
            const int c  = cp * 32 + cl;
            const int off = hw0 + ((t >> 3) * IMG) + (t & 7);
            const size_t ga = xbase + (size_t)c * IMG * IMG + off;
            out[ga] = QS[t * 33 + cl] + bo[c] + x[ga];
        }
        __syncthreads();
    }
}

// ---------------------------------------------------------------------------
extern "C" void kernel_launch(void* const* d_in, const int* in_sizes, int n_in,
                              void* d_out, int out_size)
{
    const float* x    = (const float*)d_in[0];
    const float* gnw  = (const float*)d_in[1];
    const float* gnb  = (const float*)d_in[2];
    const float* Wq   = (const float*)d_in[3];
    const float* Wk   = (const float*)d_in[4];
    const float* Wv   = (const float*)d_in[5];
    const float* Wo   = (const float*)d_in[6];
    const float* bo   = (const float*)d_in[7];
    const float* pos  = (const float*)d_in[8];
    const float* scl  = (const float*)d_in[9];
    float* out = (float*)d_out;

    const int smem_bytes = SMEM_FLOATS * sizeof(float); // 208896
    cudaFuncSetAttribute(win_attn_kernel,
                         cudaFuncAttributeMaxDynamicSharedMemorySize,
                         smem_bytes);

    gn_stats_kernel<<<BATCH * NGROUP, 512>>>(x);
    win_attn_kernel<<<BATCH * (IMG / WSZ) * (IMG / WSZ), 256, smem_bytes>>>(
        x, gnw, gnb, Wq, Wk, Wv, Wo, bo, pos, scl, out);
}

// round 5
// speedup vs baseline: 1.1297x; 1.1297x over previous
#include <cuda_runtime.h>
#include <cstdint>

#define BATCH  4
#define CH     256
#define IMG    256
#define NGROUP 32
#define CPG    8
#define WSZ    8
#define NT     64
#define NHEAD  8
#define DHEAD  32
#define GN_EPS 1e-5f

__device__ float g_mean[BATCH * NGROUP];
__device__ float g_rstd[BATCH * NGROUP];

// ---------------------------------------------------------------------------
// Kernel 1: GroupNorm statistics (unchanged; HBM-bound, ~60-90us)
// ---------------------------------------------------------------------------
__global__ void gn_stats_kernel(const float* __restrict__ x)
{
    const int bg = blockIdx.x;
    const float4* p = reinterpret_cast<const float4*>(x + (size_t)bg * CPG * IMG * IMG);
    const int n4 = (CPG * IMG * IMG) / 4;

    float s = 0.f, sq = 0.f;
    for (int i = threadIdx.x; i < n4; i += blockDim.x) {
        float4 v = p[i];
        s  += v.x + v.y + v.z + v.w;
        sq += v.x * v.x + v.y * v.y + v.z * v.z + v.w * v.w;
    }
    for (int o = 16; o; o >>= 1) {
        s  += __shfl_down_sync(0xFFFFFFFFu, s,  o);
        sq += __shfl_down_sync(0xFFFFFFFFu, sq, o);
    }
    __shared__ float ss[32], ssq[32];
    const int w = threadIdx.x >> 5, l = threadIdx.x & 31;
    if (l == 0) { ss[w] = s; ssq[w] = sq; }
    __syncthreads();
    if (w == 0) {
        const int nw = blockDim.x >> 5;
        s  = (l < nw) ? ss[l]  : 0.f;
        sq = (l < nw) ? ssq[l] : 0.f;
        for (int o = 16; o; o >>= 1) {
            s  += __shfl_down_sync(0xFFFFFFFFu, s,  o);
            sq += __shfl_down_sync(0xFFFFFFFFu, sq, o);
        }
        if (l == 0) {
            const float invN = 1.f / (float)(CPG * IMG * IMG);
            const float m   = s * invN;
            const float var = sq * invN - m * m;
            g_mean[bg] = m;
            g_rstd[bg] = rsqrtf(var + GN_EPS);
        }
    }
}

// ---------------------------------------------------------------------------
// tf32 mma helpers
// ---------------------------------------------------------------------------
__device__ __forceinline__ uint32_t f2tf(float f) {
    uint32_t u; asm("cvt.rna.tf32.f32 %0, %1;" : "=r"(u) : "f"(f)); return u;
}
__device__ __forceinline__ void f2tf2(float f, uint32_t& h, uint32_t& l) {
    asm("cvt.rna.tf32.f32 %0, %1;" : "=r"(h) : "f"(f));
    float r = f - __uint_as_float(h);
    asm("cvt.rna.tf32.f32 %0, %1;" : "=r"(l) : "f"(r));
}
__device__ __forceinline__ void mma_tf32(float d[4],
    uint32_t a0, uint32_t a1, uint32_t a2, uint32_t a3,
    uint32_t b0, uint32_t b1)
{
    asm("mma.sync.aligned.m16n8k8.row.col.f32.tf32.tf32.f32 "
        "{%0,%1,%2,%3},{%4,%5,%6,%7},{%8,%9},{%0,%1,%2,%3};"
        : "+f"(d[0]), "+f"(d[1]), "+f"(d[2]), "+f"(d[3])
        : "r"(a0), "r"(a1), "r"(a2), "r"(a3), "r"(b0), "r"(b1));
}

// ---------------------------------------------------------------------------
// Kernel 2: fused window attention on tensor cores (tf32 / 3xTF32).
// One block per 8x8 window. 256 threads = 8 warps.
//
// smem floats (strides all ≡ 4 mod 32 -> conflict-free fragment LDS):
//   XIN [64][260]  normalized input, fp32
//   OF  [64][260]  per-head attention outputs, fp32
//   WP  panel: QKV chunks as [96][68]; out-proj as [32][260]
//   QS  [64][36]   Q (and out-proj staging)
//   KS  [64][36]   K
//   VT  [32][68]   V transposed [d][token]
//   SS  [64][68]   pos+scores / probs
// ---------------------------------------------------------------------------
#define XIN_OFF 0
#define OF_OFF  16640
#define WP_OFF  33280
#define QS_OFF  41600
#define KS_OFF  43904
#define VT_OFF  46208
#define SS_OFF  48384
#define SMEM_FLOATS 52736   // 210944 bytes

__global__ void __launch_bounds__(256, 1)
win_attn_kernel(const float* __restrict__ x,
                const float* __restrict__ gnw, const float* __restrict__ gnb,
                const float* __restrict__ Wq,  const float* __restrict__ Wk,
                const float* __restrict__ Wv,  const float* __restrict__ Wo,
                const float* __restrict__ bo,  const float* __restrict__ pos,
                const float* __restrict__ scale,
                float* __restrict__ out)
{
    extern __shared__ float sm[];
    float* XIN = sm + XIN_OFF;
    float* OF  = sm + OF_OFF;
    float* WP  = sm + WP_OFF;
    float* QS  = sm + QS_OFF;
    float* KS  = sm + KS_OFF;
    float* VT  = sm + VT_OFF;
    float* SS  = sm + SS_OFF;

    const int tid  = threadIdx.x;
    const int wid  = tid >> 5;
    const int lane = tid & 31;
    const int g    = lane >> 2;     // fragment group row
    const int tg   = lane & 3;      // thread-in-group

    const int bid = blockIdx.x;
    const int b   = bid >> 10;
    const int wh  = (bid >> 5) & 31;
    const int ww  = bid & 31;
    const size_t xbase = (size_t)b * CH * IMG * IMG;
    const int    hw0   = (wh * WSZ) * IMG + ww * WSZ;

    const float qscale = scale[0];

    // ---- load window + GroupNorm -> XIN (fp32) ----
    for (int idx = tid; idx < NT * CH; idx += 256) {
        const int c = idx >> 6;
        const int t = idx & 63;
        const int off = hw0 + ((t >> 3) * IMG) + (t & 7);
        const float v = x[xbase + (size_t)c * IMG * IMG + off];
        const int gg = c >> 3;
        XIN[t * 260 + c] = (v - g_mean[b * NGROUP + gg]) * g_rstd[b * NGROUP + gg]
                           * gnw[c] + gnb[c];
    }

    // warp tile assignments
    const int m0 = (wid & 1) * 32;       // QKV: two m-tiles (rows m0..m0+31)
    const int nj = wid >> 1;             // QKV: n-tiles 3*nj .. 3*nj+2 (of 12)
    const int ms = (wid >> 1) * 16;      // S:   one m-tile
    const int nq = (wid & 1) * 4;        // S:   4 n-tiles (of 8)
    const int mo = (wid >> 1) * 16;      // O / out-proj: one m-tile
    const int np = (wid & 1) * 2;        // O / out-proj: 2 n-tiles (of 4)

    // ================= per-head attention =================
    for (int h = 0; h < NHEAD; h++) {
        const int r0 = h * DHEAD;

        // ---- QKV merged GEMM: [64 x 96] = XIN[64x256] @ Wqkv^T, 3xTF32 for Q,K ----
        float acc[2][3][4];
        #pragma unroll
        for (int mi = 0; mi < 2; mi++)
            #pragma unroll
            for (int j = 0; j < 3; j++)
                #pragma unroll
                for (int z = 0; z < 4; z++) acc[mi][j][z] = 0.f;

        for (int kc = 0; kc < 4; kc++) {
            const int k0 = kc * 64;
            __syncthreads();                       // WP free (prev readers done)
            for (int i = tid; i < 96 * 64; i += 256) {
                const int rrow = i >> 6, kk = i & 63;
                const float* src = (rrow < 32) ? Wq : ((rrow < 64) ? Wk : Wv);
                WP[rrow * 68 + kk] = src[(size_t)(r0 + (rrow & 31)) * 256 + k0 + kk];
            }
            __syncthreads();

            for (int ks = 0; ks < 8; ks++) {
                const int kk = ks * 8;
                uint32_t ah[2][4], al[2][4];
                #pragma unroll
                for (int mi = 0; mi < 2; mi++) {
                    const float* Ap = &XIN[(m0 + mi * 16 + g) * 260 + k0 + kk + tg];
                    f2tf2(Ap[0],          ah[mi][0], al[mi][0]);
                    f2tf2(Ap[8 * 260],    ah[mi][1], al[mi][1]);
                    f2tf2(Ap[4],          ah[mi][2], al[mi][2]);
                    f2tf2(Ap[8 * 260 + 4],ah[mi][3], al[mi][3]);
                }
                #pragma unroll
                for (int j = 0; j < 3; j++) {
                    const int ntg = nj * 3 + j;
                    const float* Bp = &WP[(ntg * 8 + g) * 68 + kk + tg];
                    if (ntg < 8) {                 // Q/K: 3xTF32 (accurate)
                        uint32_t bh0, bl0, bh1, bl1;
                        f2tf2(Bp[0], bh0, bl0);
                        f2tf2(Bp[4], bh1, bl1);
                        #pragma unroll
                        for (int mi = 0; mi < 2; mi++) {
                            mma_tf32(acc[mi][j], ah[mi][0], ah[mi][1], ah[mi][2], ah[mi][3], bh0, bh1);
                            mma_tf32(acc[mi][j], al[mi][0], al[mi][1], al[mi][2], al[mi][3], bh0, bh1);
                            mma_tf32(acc[mi][j], ah[mi][0], ah[mi][1], ah[mi][2], ah[mi][3], bl0, bl1);
                        }
                    } else {                       // V: plain tf32
                        const uint32_t b0 = f2tf(Bp[0]), b1 = f2tf(Bp[4]);
                        #pragma unroll
                        for (int mi = 0; mi < 2; mi++)
                            mma_tf32(acc[mi][j], ah[mi][0], ah[mi][1], ah[mi][2], ah[mi][3], b0, b1);
                    }
                }
            }
        }

        // store Q -> QS (x qscale), K -> KS, V -> VT (transposed)
        #pragma unroll
        for (int mi = 0; mi < 2; mi++) {
            const int row = m0 + mi * 16 + g;
            #pragma unroll
            for (int j = 0; j < 3; j++) {
                const int ntg = nj * 3 + j;
                float d0 = acc[mi][j][0], d1 = acc[mi][j][1];
                float d2 = acc[mi][j][2], d3 = acc[mi][j][3];
                if (ntg < 4) {
                    d0 *= qscale; d1 *= qscale; d2 *= qscale; d3 *= qscale;
                    const int c = ntg * 8 + 2 * tg;
                    *(float2*)&QS[row * 36 + c]       = make_float2(d0, d1);
                    *(float2*)&QS[(row + 8) * 36 + c] = make_float2(d2, d3);
                } else if (ntg < 8) {
                    const int c = (ntg - 4) * 8 + 2 * tg;
                    *(float2*)&KS[row * 36 + c]       = make_float2(d0, d1);
                    *(float2*)&KS[(row + 8) * 36 + c] = make_float2(d2, d3);
                } else {
                    const int c = (ntg - 8) * 8 + 2 * tg;
                    VT[c * 68 + row]           = d0;
                    VT[(c + 1) * 68 + row]     = d1;
                    VT[c * 68 + row + 8]       = d2;
                    VT[(c + 1) * 68 + row + 8] = d3;
                }
            }
        }
        __syncthreads();

        // ---- pos_emb -> SS, then S = Q K^T (3xTF32) accumulated in regs ----
        for (int i = tid; i < 4096; i += 256)
            SS[(i >> 6) * 68 + (i & 63)] = pos[h * 4096 + i];

        float sacc[4][4];
        #pragma unroll
        for (int j = 0; j < 4; j++)
            #pragma unroll
            for (int z = 0; z < 4; z++) sacc[j][z] = 0.f;

        for (int ks = 0; ks < 4; ks++) {
            const int kk = ks * 8;
            uint32_t qh[4], ql[4];
            const float* Qp = &QS[(ms + g) * 36 + kk + tg];
            f2tf2(Qp[0],          qh[0], ql[0]);
            f2tf2(Qp[8 * 36],     qh[1], ql[1]);
            f2tf2(Qp[4],          qh[2], ql[2]);
            f2tf2(Qp[8 * 36 + 4], qh[3], ql[3]);
            #pragma unroll
            for (int j = 0; j < 4; j++) {
                const float* Kp = &KS[((nq + j) * 8 + g) * 36 + kk + tg];
                uint32_t kh0, kl0, kh1, kl1;
                f2tf2(Kp[0], kh0, kl0);
                f2tf2(Kp[4], kh1, kl1);
                mma_tf32(sacc[j], qh[0], qh[1], qh[2], qh[3], kh0, kh1);
                mma_tf32(sacc[j], ql[0], ql[1], ql[2], ql[3], kh0, kh1);
                mma_tf32(sacc[j], qh[0], qh[1], qh[2], qh[3], kl0, kl1);
            }
        }
        __syncthreads();                           // pos stores visible

        #pragma unroll
        for (int j = 0; j < 4; j++) {
            const int c = (nq + j) * 8 + 2 * tg;
            const int row = ms + g;
            float2* p0 = (float2*)&SS[row * 68 + c];
            float2 v0 = *p0; v0.x += sacc[j][0]; v0.y += sacc[j][1]; *p0 = v0;
            float2* p1 = (float2*)&SS[(row + 8) * 68 + c];
            float2 v1 = *p1; v1.x += sacc[j][2]; v1.y += sacc[j][3]; *p1 = v1;
        }
        __syncthreads();

        // ---- softmax: 2 threads per row, shfl-combined ----
        if (tid < 128) {
            const int row = tid >> 1, half = tid & 1;
            float* p = &SS[row * 68 + half * 32];
            float m = -1e30f;
            #pragma unroll 8
            for (int j = 0; j < 32; j++) m = fmaxf(m, p[j]);
            m = fmaxf(m, __shfl_xor_sync(0xFFFFFFFFu, m, 1));
            float s = 0.f;
            #pragma unroll 8
            for (int j = 0; j < 32; j++) { const float e = __expf(p[j] - m); p[j] = e; s += e; }
            s += __shfl_xor_sync(0xFFFFFFFFu, s, 1);
            const float inv = 1.f / s;
            #pragma unroll 8
            for (int j = 0; j < 32; j++) p[j] *= inv;
        }
        __syncthreads();

        // ---- O = S @ V (plain tf32) -> OF[:, r0:r0+32] ----
        float oacc[2][4];
        #pragma unroll
        for (int j = 0; j < 2; j++)
            #pragma unroll
            for (int z = 0; z < 4; z++) oacc[j][z] = 0.f;

        for (int ks = 0; ks < 8; ks++) {
            const int kk = ks * 8;
            const float* Sp = &SS[(mo + g) * 68 + kk + tg];
            const uint32_t a0 = f2tf(Sp[0]),          a1 = f2tf(Sp[8 * 68]);
            const uint32_t a2 = f2tf(Sp[4]),          a3 = f2tf(Sp[8 * 68 + 4]);
            #pragma unroll
            for (int j = 0; j < 2; j++) {
                const float* Vp = &VT[((np + j) * 8 + g) * 68 + kk + tg];
                mma_tf32(oacc[j], a0, a1, a2, a3, f2tf(Vp[0]), f2tf(Vp[4]));
            }
        }
        #pragma unroll
        for (int j = 0; j < 2; j++) {
            const int c = r0 + (np + j) * 8 + 2 * tg;
            const int row = mo + g;
            *(float2*)&OF[row * 260 + c]       = make_float2(oacc[j][0], oacc[j][1]);
            *(float2*)&OF[(row + 8) * 260 + c] = make_float2(oacc[j][2], oacc[j][3]);
        }
        // next iteration's first __syncthreads() orders OF/SS/VT reuse
    }

    // ================= out projection (plain tf32) + bias + residual =========
    for (int cp = 0; cp < 8; cp++) {
        __syncthreads();                            // prev writeout / OF stores done
        for (int i = tid; i < 32 * 256; i += 256) {
            const int rrow = i >> 8, kk = i & 255;
            WP[rrow * 260 + kk] = Wo[(size_t)(cp * 32 + rrow) * 256 + kk];
        }
        __syncthreads();

        float pacc[2][4];
        #pragma unroll
        for (int j = 0; j < 2; j++)
            #pragma unroll
            for (int z = 0; z < 4; z++) pacc[j][z] = 0.f;

        for (int ks = 0; ks < 32; ks++) {
            const int kk = ks * 8;
            const float* Ap = &OF[(mo + g) * 260 + kk + tg];
            const uint32_t a0 = f2tf(Ap[0]),           a1 = f2tf(Ap[8 * 260]);
            const uint32_t a2 = f2tf(Ap[4]),           a3 = f2tf(Ap[8 * 260 + 4]);
            #pragma unroll
            for (int j = 0; j < 2; j++) {
                const float* Bp = &WP[((np + j) * 8 + g) * 260 + kk + tg];
                mma_tf32(pacc[j], a0, a1, a2, a3, f2tf(Bp[0]), f2tf(Bp[4]));
            }
        }
        // stage into QS [64][36]
        #pragma unroll
        for (int j = 0; j < 2; j++) {
            const int c = (np + j) * 8 + 2 * tg;
            const int row = mo + g;
            *(float2*)&QS[row * 36 + c]       = make_float2(pacc[j][0], pacc[j][1]);
            *(float2*)&QS[(row + 8) * 36 + c] = make_float2(pacc[j][2], pacc[j][3]);
        }
        __syncthreads();

        // coalesced writeout with bias + residual
        for (int idx = tid; idx < NT * 32; idx += 256) {
            const int cl = idx >> 6;
            const int t  = idx & 63;
            const int c  = cp * 32 + cl;
            const int off = hw0 + ((t >> 3) * IMG) + (t & 7);
            const size_t ga = xbase + (size_t)c * IMG * IMG + off;
            out[ga] = QS[t * 36 + cl] + bo[c] + x[ga];
        }
    }
}

// ---------------------------------------------------------------------------
extern "C" void kernel_launch(void* const* d_in, const int* in_sizes, int n_in,
                              void* d_out, int out_size)
{
    const float* x    = (const float*)d_in[0];
    const float* gnw  = (const float*)d_in[1];
    const float* gnb  = (const float*)d_in[2];
    const float* Wq   = (const float*)d_in[3];
    const float* Wk   = (const float*)d_in[4];
    const float* Wv   = (const float*)d_in[5];
    const float* Wo   = (const float*)d_in[6];
    const float* bo   = (const float*)d_in[7];
    const float* pos  = (const float*)d_in[8];
    const float* scl  = (const float*)d_in[9];
    float* out = (float*)d_out;

    const int smem_bytes = SMEM_FLOATS * sizeof(float); // 210944
    cudaFuncSetAttribute(win_attn_kernel,
                         cudaFuncAttributeMaxDynamicSharedMemorySize,
                         smem_bytes);

    gn_stats_kernel<<<BATCH * NGROUP, 512>>>(x);
    win_attn_kernel<<<BATCH * (IMG / WSZ) * (IMG / WSZ), 256, smem_bytes>>>(
        x, gnw, gnb, Wq, Wk, Wv, Wo, bo, pos, scl, out);
}

// round 6
// speedup vs baseline: 1.5312x; 1.3554x over previous
#include <cuda_runtime.h>
#include <cstdint>

#define BATCH  4
#define CH     256
#define IMG    256
#define WSZ    8
#define NT     64
#define NHEAD  8
#define GN_EPS 1e-5f

#define NTOK   (BATCH * IMG * IMG)          // 262144 tokens
#define QKV_N  768

// ---- scratch (device globals; allocation is banned) ----
__device__ float g_mean[BATCH * 32];
__device__ float g_rstd[BATCH * 32];
__device__ float g_qkv[(size_t)NTOK * QKV_N];   // 805 MB: [token][Q 256 | K 256 | V 256]
__device__ float g_att[(size_t)NTOK * CH];      // 268 MB: attention output per token

// ---------------------------------------------------------------------------
// helpers
// ---------------------------------------------------------------------------
__device__ __forceinline__ uint32_t f2tf(float f) {
    uint32_t u; asm("cvt.rna.tf32.f32 %0, %1;" : "=r"(u) : "f"(f)); return u;
}
__device__ __forceinline__ void f2tf2(float f, uint32_t& h, uint32_t& l) {
    asm("cvt.rna.tf32.f32 %0, %1;" : "=r"(h) : "f"(f));
    float r = f - __uint_as_float(h);
    asm("cvt.rna.tf32.f32 %0, %1;" : "=r"(l) : "f"(r));
}
__device__ __forceinline__ void mma_tf32(float d[4],
    uint32_t a0, uint32_t a1, uint32_t a2, uint32_t a3,
    uint32_t b0, uint32_t b1)
{
    asm("mma.sync.aligned.m16n8k8.row.col.f32.tf32.tf32.f32 "
        "{%0,%1,%2,%3},{%4,%5,%6,%7},{%8,%9},{%0,%1,%2,%3};"
        : "+f"(d[0]), "+f"(d[1]), "+f"(d[2]), "+f"(d[3])
        : "r"(a0), "r"(a1), "r"(a2), "r"(a3), "r"(b0), "r"(b1));
}
// token m -> pixel offset (within one image plane) and batch
__device__ __forceinline__ void tok2pix(int m, int& b, int& pix) {
    b = m >> 16;
    const int win = (m >> 6) & 1023;
    const int t   = m & 63;
    pix = ((win >> 5) * WSZ + (t >> 3)) * IMG + (win & 31) * WSZ + (t & 7);
}

// ---------------------------------------------------------------------------
// K1: GroupNorm statistics
// ---------------------------------------------------------------------------
__global__ void gn_stats_kernel(const float* __restrict__ x)
{
    const int bg = blockIdx.x;
    const float4* p = reinterpret_cast<const float4*>(x + (size_t)bg * 8 * IMG * IMG);
    const int n4 = (8 * IMG * IMG) / 4;

    float s = 0.f, sq = 0.f;
    for (int i = threadIdx.x; i < n4; i += blockDim.x) {
        float4 v = p[i];
        s  += v.x + v.y + v.z + v.w;
        sq += v.x * v.x + v.y * v.y + v.z * v.z + v.w * v.w;
    }
    for (int o = 16; o; o >>= 1) {
        s  += __shfl_down_sync(0xFFFFFFFFu, s,  o);
        sq += __shfl_down_sync(0xFFFFFFFFu, sq, o);
    }
    __shared__ float ss[32], ssq[32];
    const int w = threadIdx.x >> 5, l = threadIdx.x & 31;
    if (l == 0) { ss[w] = s; ssq[w] = sq; }
    __syncthreads();
    if (w == 0) {
        const int nw = blockDim.x >> 5;
        s  = (l < nw) ? ss[l]  : 0.f;
        sq = (l < nw) ? ssq[l] : 0.f;
        for (int o = 16; o; o >>= 1) {
            s  += __shfl_down_sync(0xFFFFFFFFu, s,  o);
            sq += __shfl_down_sync(0xFFFFFFFFu, sq, o);
        }
        if (l == 0) {
            const float invN = 1.f / (float)(8 * IMG * IMG);
            const float m   = s * invN;
            const float var = sq * invN - m * m;
            g_mean[bg] = m;
            g_rstd[bg] = rsqrtf(var + GN_EPS);
        }
    }
}

// ---------------------------------------------------------------------------
// K2: QKV projection GEMM.  g_qkv[m][0:768] = GN(x)[m][:] @ [Wq;Wk;Wv]^T
// CTA tile 128m x 64n, K chunked by 64. Q/K columns (n<512): 3xTF32.
// A,B stored in smem as interleaved (hi,lo) uint2 with XOR swizzle:
//   word index = row*136 + ( (2k) ^ ((row&7)<<1) )
// -> fills are STS.64 (2-way conflict), fragment loads LDS.64 conflict-free.
// ---------------------------------------------------------------------------
__global__ void __launch_bounds__(256, 2)
qkv_gemm_kernel(const float* __restrict__ x,
                const float* __restrict__ gnw, const float* __restrict__ gnb,
                const float* __restrict__ Wq,  const float* __restrict__ Wk,
                const float* __restrict__ Wv,  const float* __restrict__ scale)
{
    extern __shared__ uint32_t sm2[];
    uint32_t* As = sm2;               // 128*136
    uint32_t* Bs = sm2 + 128 * 136;   // 64*136

    const int tid  = threadIdx.x;
    const int wid  = tid >> 5, lane = tid & 31;
    const int g    = lane >> 2, tg = lane & 3;

    const int m0 = blockIdx.x * 128;
    const int n0 = blockIdx.y * 64;
    const bool is3x = (n0 < 512);
    const float* Wsrc = (n0 < 256) ? Wq : (n0 < 512 ? Wk : Wv);
    const int wrow0 = n0 & 255;

    // per-thread token for A loads
    const int arow = tid & 127;
    int b, pix; tok2pix(m0 + arow, b, pix);
    const size_t xoff = (size_t)b * CH * IMG * IMG + pix;
    const int kstart = tid >> 7;          // 0 or 1

    const int wm = (wid & 3) * 32;
    const int wn = (wid >> 2) * 32;

    float acc[2][4][4] = {};

    for (int kc = 0; kc < 4; kc++) {
        const int k0 = kc * 64;
        __syncthreads();
        // ---- fill A (with GroupNorm + tf32 hi/lo split) ----
        #pragma unroll 4
        for (int k = kstart; k < 64; k += 2) {
            const int c = k0 + k;
            const float v = x[xoff + (size_t)c * (IMG * IMG)];
            const float xn = (v - g_mean[b * 32 + (c >> 3)]) * g_rstd[b * 32 + (c >> 3)]
                             * gnw[c] + gnb[c];
            uint32_t h, l; f2tf2(xn, h, l);
            const int col = (2 * k) ^ ((arow & 7) << 1);
            *reinterpret_cast<uint2*>(&As[arow * 136 + col]) = make_uint2(h, l);
        }
        // ---- fill B ----
        for (int idx = tid; idx < 64 * 64; idx += 256) {
            const int r = idx >> 6, k = idx & 63;
            uint32_t h, l; f2tf2(Wsrc[(size_t)(wrow0 + r) * 256 + k0 + k], h, l);
            const int col = (2 * k) ^ ((r & 7) << 1);
            *reinterpret_cast<uint2*>(&Bs[r * 136 + col]) = make_uint2(h, l);
        }
        __syncthreads();
        // ---- compute ----
        #pragma unroll
        for (int ks = 0; ks < 8; ks++) {
            const int kk = ks * 8;
            const int c0 = (2 * (kk + tg))     ^ (g << 1);
            const int c2 = (2 * (kk + tg + 4)) ^ (g << 1);
            uint2 a0[2], a1[2], a2[2], a3[2];
            #pragma unroll
            for (int mi = 0; mi < 2; mi++) {
                const int r = wm + mi * 16 + g;
                a0[mi] = *reinterpret_cast<const uint2*>(&As[r * 136 + c0]);
                a2[mi] = *reinterpret_cast<const uint2*>(&As[r * 136 + c2]);
                a1[mi] = *reinterpret_cast<const uint2*>(&As[(r + 8) * 136 + c0]);
                a3[mi] = *reinterpret_cast<const uint2*>(&As[(r + 8) * 136 + c2]);
            }
            #pragma unroll
            for (int nj = 0; nj < 4; nj++) {
                const int n = wn + nj * 8 + g;
                const uint2 b0 = *reinterpret_cast<const uint2*>(&Bs[n * 136 + c0]);
                const uint2 b1 = *reinterpret_cast<const uint2*>(&Bs[n * 136 + c2]);
                #pragma unroll
                for (int mi = 0; mi < 2; mi++) {
                    mma_tf32(acc[mi][nj], a0[mi].x, a1[mi].x, a2[mi].x, a3[mi].x, b0.x, b1.x);
                    if (is3x) {
                        mma_tf32(acc[mi][nj], a0[mi].y, a1[mi].y, a2[mi].y, a3[mi].y, b0.x, b1.x);
                        mma_tf32(acc[mi][nj], a0[mi].x, a1[mi].x, a2[mi].x, a3[mi].x, b0.y, b1.y);
                    }
                }
            }
        }
    }
    // ---- epilogue: Q gets qscale ----
    const float mul = (n0 < 256) ? scale[0] : 1.0f;
    #pragma unroll
    for (int mi = 0; mi < 2; mi++) {
        const int r = wm + mi * 16 + g;
        #pragma unroll
        for (int nj = 0; nj < 4; nj++) {
            const int cc = n0 + wn + nj * 8 + 2 * tg;
            *reinterpret_cast<float2*>(&g_qkv[(size_t)(m0 + r) * QKV_N + cc]) =
                make_float2(acc[mi][nj][0] * mul, acc[mi][nj][1] * mul);
            *reinterpret_cast<float2*>(&g_qkv[(size_t)(m0 + r + 8) * QKV_N + cc]) =
                make_float2(acc[mi][nj][2] * mul, acc[mi][nj][3] * mul);
        }
    }
}

// ---------------------------------------------------------------------------
// K3: per-window attention. One block per window (4096 blocks, 256 thr).
// smem floats: QS[64][36] KS[64][36] VT[32][69] SS[64][68] = 11168 (44.7 KB)
// ---------------------------------------------------------------------------
__global__ void __launch_bounds__(256)
attn_kernel(const float* __restrict__ pos)
{
    extern __shared__ float sm[];
    float* QS = sm;
    float* KS = sm + 2304;
    float* VT = sm + 4608;
    float* SS = sm + 6816;

    const int tid = threadIdx.x;
    const int wid = tid >> 5, lane = tid & 31;
    const int g = lane >> 2, tg = lane & 3;
    const int m0 = blockIdx.x * NT;

    const int ms = (wid >> 1) * 16;   // S gemm m-tile
    const int nq = (wid & 1) * 4;     // S gemm: 4 n-tiles
    const int np = (wid & 1) * 2;     // O gemm: 2 n-tiles

    for (int h = 0; h < NHEAD; h++) {
        __syncthreads();              // protect smem reuse across heads
        // ---- load Q,K,V (coalesced 128B rows) + stage pos into SS ----
        for (int idx = tid; idx < 2048; idx += 256) {
            const int t = idx >> 5, d = idx & 31;
            const float* base = &g_qkv[(size_t)(m0 + t) * QKV_N + h * 32 + d];
            QS[t * 36 + d] = base[0];
            KS[t * 36 + d] = base[256];
            VT[d * 69 + t] = base[512];
        }
        for (int i = tid; i < 4096; i += 256)
            SS[(i >> 6) * 68 + (i & 63)] = pos[h * 4096 + i];
        __syncthreads();

        // ---- S = Q K^T (3xTF32) ----
        float sacc[4][4];
        #pragma unroll
        for (int j = 0; j < 4; j++)
            #pragma unroll
            for (int z = 0; z < 4; z++) sacc[j][z] = 0.f;

        #pragma unroll
        for (int ks = 0; ks < 4; ks++) {
            const int kk = ks * 8;
            uint32_t qh[4], ql[4];
            const float* Qp = &QS[(ms + g) * 36 + kk + tg];
            f2tf2(Qp[0],          qh[0], ql[0]);
            f2tf2(Qp[8 * 36],     qh[1], ql[1]);
            f2tf2(Qp[4],          qh[2], ql[2]);
            f2tf2(Qp[8 * 36 + 4], qh[3], ql[3]);
            #pragma unroll
            for (int j = 0; j < 4; j++) {
                const float* Kp = &KS[((nq + j) * 8 + g) * 36 + kk + tg];
                uint32_t kh0, kl0, kh1, kl1;
                f2tf2(Kp[0], kh0, kl0);
                f2tf2(Kp[4], kh1, kl1);
                mma_tf32(sacc[j], qh[0], qh[1], qh[2], qh[3], kh0, kh1);
                mma_tf32(sacc[j], ql[0], ql[1], ql[2], ql[3], kh0, kh1);
                mma_tf32(sacc[j], qh[0], qh[1], qh[2], qh[3], kl0, kl1);
            }
        }
        // SS += sacc  (each warp owns rows ms..ms+15 for its nq columns)
        #pragma unroll
        for (int j = 0; j < 4; j++) {
            const int c = (nq + j) * 8 + 2 * tg;
            const int row = ms + g;
            float2* p0 = (float2*)&SS[row * 68 + c];
            float2 v0 = *p0; v0.x += sacc[j][0]; v0.y += sacc[j][1]; *p0 = v0;
            float2* p1 = (float2*)&SS[(row + 8) * 68 + c];
            float2 v1 = *p1; v1.x += sacc[j][2]; v1.y += sacc[j][3]; *p1 = v1;
        }
        __syncthreads();

        // ---- softmax (2 threads per row) ----
        if (tid < 128) {
            const int row = tid >> 1, half = tid & 1;
            float* p = &SS[row * 68 + half * 32];
            float m = -1e30f;
            #pragma unroll 8
            for (int j = 0; j < 32; j++) m = fmaxf(m, p[j]);
            m = fmaxf(m, __shfl_xor_sync(0xFFFFFFFFu, m, 1));
            float s = 0.f;
            #pragma unroll 8
            for (int j = 0; j < 32; j++) { const float e = __expf(p[j] - m); p[j] = e; s += e; }
            s += __shfl_xor_sync(0xFFFFFFFFu, s, 1);
            const float inv = 1.f / s;
            #pragma unroll 8
            for (int j = 0; j < 32; j++) p[j] *= inv;
        }
        __syncthreads();

        // ---- O = S @ V (plain tf32) -> g_att ----
        float oacc[2][4];
        #pragma unroll
        for (int j = 0; j < 2; j++)
            #pragma unroll
            for (int z = 0; z < 4; z++) oacc[j][z] = 0.f;

        #pragma unroll
        for (int ks = 0; ks < 8; ks++) {
            const int kk = ks * 8;
            const float* Sp = &SS[(ms + g) * 68 + kk + tg];
            const uint32_t a0 = f2tf(Sp[0]),     a1 = f2tf(Sp[8 * 68]);
            const uint32_t a2 = f2tf(Sp[4]),     a3 = f2tf(Sp[8 * 68 + 4]);
            #pragma unroll
            for (int j = 0; j < 2; j++) {
                const float* Vp = &VT[((np + j) * 8 + g) * 69 + kk + tg];
                mma_tf32(oacc[j], a0, a1, a2, a3, f2tf(Vp[0]), f2tf(Vp[4]));
            }
        }
        #pragma unroll
        for (int j = 0; j < 2; j++) {
            const int c = h * 32 + (np + j) * 8 + 2 * tg;
            const int row = ms + g;
            *reinterpret_cast<float2*>(&g_att[(size_t)(m0 + row) * CH + c]) =
                make_float2(oacc[j][0], oacc[j][1]);
            *reinterpret_cast<float2*>(&g_att[(size_t)(m0 + row + 8) * CH + c]) =
                make_float2(oacc[j][2], oacc[j][3]);
        }
    }
}

// ---------------------------------------------------------------------------
// K4: output projection (plain tf32) + bias + residual + scatter to NCHW.
// CTA tile 128m x 64n. smem: As[128][68] + Bs[64][68] = 52 KB.
// ---------------------------------------------------------------------------
__global__ void __launch_bounds__(256, 3)
outproj_kernel(const float* __restrict__ x, const float* __restrict__ Wo,
               const float* __restrict__ bo, float* __restrict__ out)
{
    extern __shared__ float smf[];
    float* As = smf;              // [128][68]
    float* Bs = smf + 128 * 68;   // [64][68]

    const int tid = threadIdx.x;
    const int wid = tid >> 5, lane = tid & 31;
    const int g = lane >> 2, tg = lane & 3;
    const int m0 = blockIdx.x * 128;
    const int n0 = blockIdx.y * 64;
    const int wm = (wid & 3) * 32;
    const int wn = (wid >> 2) * 32;

    float acc[2][4][4] = {};

    for (int kc = 0; kc < 4; kc++) {
        const int k0 = kc * 64;
        __syncthreads();
        for (int idx = tid; idx < 128 * 64; idx += 256) {
            const int r = idx >> 6, k = idx & 63;
            As[r * 68 + k] = __uint_as_float(f2tf(g_att[(size_t)(m0 + r) * CH + k0 + k]));
        }
        for (int idx = tid; idx < 64 * 64; idx += 256) {
            const int r = idx >> 6, k = idx & 63;
            Bs[r * 68 + k] = __uint_as_float(f2tf(Wo[(size_t)(n0 + r) * 256 + k0 + k]));
        }
        __syncthreads();
        #pragma unroll
        for (int ks = 0; ks < 8; ks++) {
            const int kk = ks * 8;
            uint32_t a[2][4];
            #pragma unroll
            for (int mi = 0; mi < 2; mi++) {
                const float* Ap = &As[(wm + mi * 16 + g) * 68 + kk + tg];
                a[mi][0] = __float_as_uint(Ap[0]);
                a[mi][1] = __float_as_uint(Ap[8 * 68]);
                a[mi][2] = __float_as_uint(Ap[4]);
                a[mi][3] = __float_as_uint(Ap[8 * 68 + 4]);
            }
            #pragma unroll
            for (int nj = 0; nj < 4; nj++) {
                const float* Bp = &Bs[((wn + nj * 8) + g) * 68 + kk + tg];
                const uint32_t b0 = __float_as_uint(Bp[0]);
                const uint32_t b1 = __float_as_uint(Bp[4]);
                #pragma unroll
                for (int mi = 0; mi < 2; mi++)
                    mma_tf32(acc[mi][nj], a[mi][0], a[mi][1], a[mi][2], a[mi][3], b0, b1);
            }
        }
    }
    // epilogue: + bias + residual, scatter to [b][c][h][w]
    #pragma unroll
    for (int mi = 0; mi < 2; mi++) {
        #pragma unroll
        for (int half = 0; half < 2; half++) {
            const int r = wm + mi * 16 + g + half * 8;
            int b, pix; tok2pix(m0 + r, b, pix);
            const size_t base = (size_t)b * CH * IMG * IMG + pix;
            #pragma unroll
            for (int nj = 0; nj < 4; nj++) {
                const int c0 = n0 + wn + nj * 8 + 2 * tg;
                const size_t a0 = base + (size_t)c0 * (IMG * IMG);
                const size_t a1 = a0 + (IMG * IMG);
                out[a0] = acc[mi][nj][half * 2 + 0] + bo[c0]     + x[a0];
                out[a1] = acc[mi][nj][half * 2 + 1] + bo[c0 + 1] + x[a1];
            }
        }
    }
}

// ---------------------------------------------------------------------------
extern "C" void kernel_launch(void* const* d_in, const int* in_sizes, int n_in,
                              void* d_out, int out_size)
{
    const float* x    = (const float*)d_in[0];
    const float* gnw  = (const float*)d_in[1];
    const float* gnb  = (const float*)d_in[2];
    const float* Wq   = (const float*)d_in[3];
    const float* Wk   = (const float*)d_in[4];
    const float* Wv   = (const float*)d_in[5];
    const float* Wo   = (const float*)d_in[6];
    const float* bo   = (const float*)d_in[7];
    const float* pos  = (const float*)d_in[8];
    const float* scl  = (const float*)d_in[9];
    float* out = (float*)d_out;

    const int smem_qkv = (128 + 64) * 136 * 4;   // 104448
    const int smem_att = 11168 * 4;              // 44672
    const int smem_out = (128 + 64) * 68 * 4;    // 52224
    cudaFuncSetAttribute(qkv_gemm_kernel, cudaFuncAttributeMaxDynamicSharedMemorySize, smem_qkv);
    cudaFuncSetAttribute(attn_kernel,     cudaFuncAttributeMaxDynamicSharedMemorySize, smem_att);
    cudaFuncSetAttribute(outproj_kernel,  cudaFuncAttributeMaxDynamicSharedMemorySize, smem_out);

    gn_stats_kernel<<<BATCH * 32, 512>>>(x);
    qkv_gemm_kernel<<<dim3(NTOK / 128, 12), 256, smem_qkv>>>(x, gnw, gnb, Wq, Wk, Wv, scl);
    attn_kernel<<<NTOK / NT, 256, smem_att>>>(pos);
    outproj_kernel<<<dim3(NTOK / 128, 4), 256, smem_out>>>(x, Wo, bo, out);
}

// round 8
// speedup vs baseline: 1.9222x; 1.2553x over previous
#include <cuda_runtime.h>
#include <cuda_bf16.h>
#include <cstdint>

#define BATCH  4
#define CH     256
#define IMG    256
#define WSZ    8
#define NT     64
#define NHEAD  8
#define GN_EPS 1e-5f

#define NTOK   (BATCH * IMG * IMG)          // 262144 tokens
#define QKV_N  768

// ---- scratch (device globals; allocation is banned) ----
__device__ float g_mean[BATCH * 32];
__device__ float g_rstd[BATCH * 32];
__device__ float g_qkv[(size_t)NTOK * QKV_N];   // [token][Q 256 | K 256 | V 256]
__device__ float g_att[(size_t)NTOK * CH];      // attention output per token

// ---------------------------------------------------------------------------
// helpers
// ---------------------------------------------------------------------------
__device__ __forceinline__ uint32_t f2tf(float f) {
    uint32_t u; asm("cvt.rna.tf32.f32 %0, %1;" : "=r"(u) : "f"(f)); return u;
}
__device__ __forceinline__ void f2tf2(float f, uint32_t& h, uint32_t& l) {
    asm("cvt.rna.tf32.f32 %0, %1;" : "=r"(h) : "f"(f));
    float r = f - __uint_as_float(h);
    asm("cvt.rna.tf32.f32 %0, %1;" : "=r"(l) : "f"(r));
}
__device__ __forceinline__ void mma_tf32(float d[4],
    uint32_t a0, uint32_t a1, uint32_t a2, uint32_t a3,
    uint32_t b0, uint32_t b1)
{
    asm("mma.sync.aligned.m16n8k8.row.col.f32.tf32.tf32.f32 "
        "{%0,%1,%2,%3},{%4,%5,%6,%7},{%8,%9},{%0,%1,%2,%3};"
        : "+f"(d[0]), "+f"(d[1]), "+f"(d[2]), "+f"(d[3])
        : "r"(a0), "r"(a1), "r"(a2), "r"(a3), "r"(b0), "r"(b1));
}
__device__ __forceinline__ void mma_bf16(float d[4], uint4 a, uint2 b)
{
    asm("mma.sync.aligned.m16n8k16.row.col.f32.bf16.bf16.f32 "
        "{%0,%1,%2,%3},{%4,%5,%6,%7},{%8,%9},{%0,%1,%2,%3};"
        : "+f"(d[0]), "+f"(d[1]), "+f"(d[2]), "+f"(d[3])
        : "r"(a.x), "r"(a.y), "r"(a.z), "r"(a.w), "r"(b.x), "r"(b.y));
}
__device__ __forceinline__ void tok2pix(int m, int& b, int& pix) {
    b = m >> 16;
    const int win = (m >> 6) & 1023;
    const int t   = m & 63;
    pix = ((win >> 5) * WSZ + (t >> 3)) * IMG + (win & 31) * WSZ + (t & 7);
}
// split fp32 pair into packed bf16x2 (hi) + bf16x2 (lo residual)
__device__ __forceinline__ uint32_t bfsplit2(float a, float b, uint32_t& lo) {
    __nv_bfloat16 ah = __float2bfloat16(a);
    __nv_bfloat16 bh = __float2bfloat16(b);
    __nv_bfloat16 al = __float2bfloat16(a - __bfloat162float(ah));
    __nv_bfloat16 bl = __float2bfloat16(b - __bfloat162float(bh));
    lo = (uint32_t)__bfloat16_as_ushort(al) | ((uint32_t)__bfloat16_as_ushort(bl) << 16);
    return (uint32_t)__bfloat16_as_ushort(ah) | ((uint32_t)__bfloat16_as_ushort(bh) << 16);
}

// ---------------------------------------------------------------------------
// K1: GroupNorm statistics
// ---------------------------------------------------------------------------
__global__ void gn_stats_kernel(const float* __restrict__ x)
{
    const int bg = blockIdx.x;
    const float4* p = reinterpret_cast<const float4*>(x + (size_t)bg * 8 * IMG * IMG);
    const int n4 = (8 * IMG * IMG) / 4;

    float s = 0.f, sq = 0.f;
    for (int i = threadIdx.x; i < n4; i += blockDim.x) {
        float4 v = p[i];
        s  += v.x + v.y + v.z + v.w;
        sq += v.x * v.x + v.y * v.y + v.z * v.z + v.w * v.w;
    }
    for (int o = 16; o; o >>= 1) {
        s  += __shfl_down_sync(0xFFFFFFFFu, s,  o);
        sq += __shfl_down_sync(0xFFFFFFFFu, sq, o);
    }
    __shared__ float ss[32], ssq[32];
    const int w = threadIdx.x >> 5, l = threadIdx.x & 31;
    if (l == 0) { ss[w] = s; ssq[w] = sq; }
    __syncthreads();
    if (w == 0) {
        const int nw = blockDim.x >> 5;
        s  = (l < nw) ? ss[l]  : 0.f;
        sq = (l < nw) ? ssq[l] : 0.f;
        for (int o = 16; o; o >>= 1) {
            s  += __shfl_down_sync(0xFFFFFFFFu, s,  o);
            sq += __shfl_down_sync(0xFFFFFFFFu, sq, o);
        }
        if (l == 0) {
            const float invN = 1.f / (float)(8 * IMG * IMG);
            const float m   = s * invN;
            const float var = sq * invN - m * m;
            g_mean[bg] = m;
            g_rstd[bg] = rsqrtf(var + GN_EPS);
        }
    }
}

// ---------------------------------------------------------------------------
// K2a: Q and K projections, 3-term split-bf16 m16n8k16.
// Grid (8, NTOK/128): blockIdx.x<4 -> Q (Wq), else K (Wk); n0=(x&3)*64.
// CTA 128m x 64n, K chunked by 64. Fragment-linear smem:
//   Ah/Al: [8 mfrag][4 ks][32 t] uint4  (16KB each)
//   Bh/Bl: [8 nfrag][4 ks][32 t] uint2  (8KB each)    total 48KB
// ---------------------------------------------------------------------------
#define QK_SMEM 49152

__global__ void __launch_bounds__(256, 3)
qk_bf16_kernel(const float* __restrict__ x,
               const float* __restrict__ gnw, const float* __restrict__ gnb,
               const float* __restrict__ Wq,  const float* __restrict__ Wk,
               const float* __restrict__ scale)
{
    extern __shared__ char smc[];
    uint4* Ah = reinterpret_cast<uint4*>(smc);
    uint4* Al = reinterpret_cast<uint4*>(smc + 16384);
    uint2* Bh = reinterpret_cast<uint2*>(smc + 32768);
    uint2* Bl = reinterpret_cast<uint2*>(smc + 40960);

    const int tid = threadIdx.x, wid = tid >> 5, lane = tid & 31;
    const bool isQ = (blockIdx.x < 4);
    const int n0 = (blockIdx.x & 3) * 64;           // weight row base (0..192)
    const int m0 = blockIdx.y * 128;
    const float* W = isQ ? Wq : Wk;

    // A fill mapping: thread -> token (tid&127), k-half (tid>>7)*32
    const int tokenL = tid & 127;
    int b, pix; tok2pix(m0 + tokenL, b, pix);
    const size_t xoff = (size_t)b * CH * IMG * IMG + pix;
    const int khalf = (tid >> 7) * 32;
    const int amfrag = tokenL >> 4;
    const int arow16 = tokenL & 15;
    const int areg_base = (arow16 >> 3) & 1;        // +0/+1
    const int at_base = (arow16 & 7) * 4;

    // B fill mapping: thread -> weight row r (tid>>2), k-quarter (tid&3)*16
    const int br = tid >> 2;
    const int bkq = (tid & 3) * 16;
    const int bnfrag = br >> 3;
    const int bt_base = (br & 7) * 4;

    const int wm = (wid & 3) * 32;                  // warp m base (2 mfrags)
    const int wn = (wid >> 2) * 32;                 // warp n base (4 nfrags)
    const int mfrag0 = wm >> 4, nfrag0 = wn >> 3;

    float acc[2][4][4] = {};

    for (int kc = 0; kc < 4; kc++) {
        const int k0 = kc * 64;
        __syncthreads();
        // ---- fill A (GN fused + bf16 split, fragment-linear) ----
        #pragma unroll 4
        for (int p = 0; p < 16; p++) {
            const int kl = khalf + 2 * p;
            const int c  = k0 + kl;
            const float v0 = x[xoff + (size_t)c * (IMG * IMG)];
            const float v1 = x[xoff + (size_t)(c + 1) * (IMG * IMG)];
            const float mn = g_mean[b * 32 + (c >> 3)];
            const float rs = g_rstd[b * 32 + (c >> 3)];
            const float xn0 = (v0 - mn) * rs * gnw[c]     + gnb[c];
            const float xn1 = (v1 - mn) * rs * gnw[c + 1] + gnb[c + 1];
            uint32_t lo; const uint32_t hi = bfsplit2(xn0, xn1, lo);
            const int ks  = kl >> 4, kin = kl & 15;
            const int slot = ((amfrag * 4 + ks) * 32 + at_base + ((kin & 7) >> 1));
            const int reg  = ((kin >> 3) & 1) * 2 + areg_base;
            reinterpret_cast<uint32_t*>(&Ah[slot])[reg] = hi;
            reinterpret_cast<uint32_t*>(&Al[slot])[reg] = lo;
        }
        // ---- fill B (weights) ----
        #pragma unroll 4
        for (int p = 0; p < 8; p++) {
            const int kl = bkq + 2 * p;
            const float2 w = *reinterpret_cast<const float2*>(
                &W[(size_t)(n0 + br) * 256 + k0 + kl]);
            uint32_t lo; const uint32_t hi = bfsplit2(w.x, w.y, lo);
            const int ks = kl >> 4, kin = kl & 15;
            const int slot = (bnfrag * 4 + ks) * 32 + bt_base + ((kin & 7) >> 1);
            const int reg  = (kin >> 3) & 1;
            reinterpret_cast<uint32_t*>(&Bh[slot])[reg] = hi;
            reinterpret_cast<uint32_t*>(&Bl[slot])[reg] = lo;
        }
        __syncthreads();
        // ---- compute: 4 k16 steps, 3-term ----
        #pragma unroll
        for (int ks = 0; ks < 4; ks++) {
            uint4 ah[2], al[2];
            #pragma unroll
            for (int mi = 0; mi < 2; mi++) {
                ah[mi] = Ah[((mfrag0 + mi) * 4 + ks) * 32 + lane];
                al[mi] = Al[((mfrag0 + mi) * 4 + ks) * 32 + lane];
            }
            uint2 bh[4], bl[4];
            #pragma unroll
            for (int nj = 0; nj < 4; nj++) {
                bh[nj] = Bh[((nfrag0 + nj) * 4 + ks) * 32 + lane];
                bl[nj] = Bl[((nfrag0 + nj) * 4 + ks) * 32 + lane];
            }
            #pragma unroll
            for (int nj = 0; nj < 4; nj++)
                #pragma unroll
                for (int mi = 0; mi < 2; mi++) {
                    mma_bf16(acc[mi][nj], ah[mi], bh[nj]);
                    mma_bf16(acc[mi][nj], al[mi], bh[nj]);
                    mma_bf16(acc[mi][nj], ah[mi], bl[nj]);
                }
        }
    }
    // ---- epilogue ----
    const float mul = isQ ? scale[0] : 1.0f;
    const int colbase = (isQ ? 0 : 256) + n0 + wn;
    #pragma unroll
    for (int mi = 0; mi < 2; mi++) {
        const int row = m0 + wm + mi * 16 + (lane >> 2);
        #pragma unroll
        for (int nj = 0; nj < 4; nj++) {
            const int c = colbase + nj * 8 + (lane & 3) * 2;
            *reinterpret_cast<float2*>(&g_qkv[(size_t)row * QKV_N + c]) =
                make_float2(acc[mi][nj][0] * mul, acc[mi][nj][1] * mul);
            *reinterpret_cast<float2*>(&g_qkv[(size_t)(row + 8) * QKV_N + c]) =
                make_float2(acc[mi][nj][2] * mul, acc[mi][nj][3] * mul);
        }
    }
}

// ---------------------------------------------------------------------------
// K2b: V projection, plain tf32 (validated R6 structure, V only).
// Grid (NTOK/128, 4). smem interleaved (hi unused-lo merged): here plain tf32
// single value per element, uint swizzled layout [row][136].
// ---------------------------------------------------------------------------
#define V_SMEM ((128 + 64) * 136 * 4)

__global__ void __launch_bounds__(256, 2)
v_gemm_kernel(const float* __restrict__ x,
              const float* __restrict__ gnw, const float* __restrict__ gnb,
              const float* __restrict__ Wv)
{
    extern __shared__ uint32_t sm2[];
    uint32_t* As = sm2;               // 128*136 (pairs of tf32: only .x used? no)
    uint32_t* Bs = sm2 + 128 * 136;

    const int tid  = threadIdx.x;
    const int wid  = tid >> 5, lane = tid & 31;
    const int g    = lane >> 2, tg = lane & 3;

    const int m0 = blockIdx.x * 128;
    const int n0 = blockIdx.y * 64;   // 0..192 within Wv

    const int arow = tid & 127;
    int b, pix; tok2pix(m0 + arow, b, pix);
    const size_t xoff = (size_t)b * CH * IMG * IMG + pix;
    const int kstart = tid >> 7;

    const int wm = (wid & 3) * 32;
    const int wn = (wid >> 2) * 32;

    float acc[2][4][4] = {};

    for (int kc = 0; kc < 4; kc++) {
        const int k0 = kc * 64;
        __syncthreads();
        #pragma unroll 4
        for (int k = kstart; k < 64; k += 2) {
            const int c = k0 + k;
            const float v = x[xoff + (size_t)c * (IMG * IMG)];
            const float xn = (v - g_mean[b * 32 + (c >> 3)]) * g_rstd[b * 32 + (c >> 3)]
                             * gnw[c] + gnb[c];
            // store tf32 value + residual-as-zero: keep uint2 slots but lo unused;
            // to save bandwidth store single word at interleave stride 2 (hi only)
            const int col = (2 * k) ^ ((arow & 7) << 1);
            As[arow * 136 + col] = f2tf(xn);
        }
        for (int idx = tid; idx < 64 * 64; idx += 256) {
            const int r = idx >> 6, k = idx & 63;
            const int col = (2 * k) ^ ((r & 7) << 1);
            Bs[r * 136 + col] = f2tf(Wv[(size_t)(n0 + r) * 256 + k0 + k]);
        }
        __syncthreads();
        #pragma unroll
        for (int ks = 0; ks < 8; ks++) {
            const int kk = ks * 8;
            const int c0 = (2 * (kk + tg))     ^ (g << 1);
            const int c2 = (2 * (kk + tg + 4)) ^ (g << 1);
            uint32_t a0[2], a1[2], a2[2], a3[2];
            #pragma unroll
            for (int mi = 0; mi < 2; mi++) {
                const int r = wm + mi * 16 + g;
                a0[mi] = As[r * 136 + c0];
                a2[mi] = As[r * 136 + c2];
                a1[mi] = As[(r + 8) * 136 + c0];
                a3[mi] = As[(r + 8) * 136 + c2];
            }
            #pragma unroll
            for (int nj = 0; nj < 4; nj++) {
                const int n = wn + nj * 8 + g;
                const uint32_t b0 = Bs[n * 136 + c0];
                const uint32_t b1 = Bs[n * 136 + c2];
                #pragma unroll
                for (int mi = 0; mi < 2; mi++)
                    mma_tf32(acc[mi][nj], a0[mi], a1[mi], a2[mi], a3[mi], b0, b1);
            }
        }
    }
    #pragma unroll
    for (int mi = 0; mi < 2; mi++) {
        const int r = wm + mi * 16 + g;
        #pragma unroll
        for (int nj = 0; nj < 4; nj++) {
            const int cc = 512 + n0 + wn + nj * 8 + 2 * tg;
            *reinterpret_cast<float2*>(&g_qkv[(size_t)(m0 + r) * QKV_N + cc]) =
                make_float2(acc[mi][nj][0], acc[mi][nj][1]);
            *reinterpret_cast<float2*>(&g_qkv[(size_t)(m0 + r + 8) * QKV_N + cc]) =
                make_float2(acc[mi][nj][2], acc[mi][nj][3]);
        }
    }
}

// ---------------------------------------------------------------------------
// K3: per-window attention. S via 3-term bf16 m16n8k16; S·V plain tf32.
// smem floats: QAh[1024] QAl[1024] KBh[1024] KBl[1024] VT[2208] SS[4352]
// = 10656 floats = 42624 B
// ---------------------------------------------------------------------------
#define AT_QAH 0
#define AT_QAL 1024
#define AT_KBH 2048
#define AT_KBL 3072
#define AT_VT  4096
#define AT_SS  6304
#define AT_SMEM (10656 * 4)

__global__ void __launch_bounds__(256)
attn_kernel(const float* __restrict__ pos)
{
    extern __shared__ float sm[];
    uint4* QAh = reinterpret_cast<uint4*>(sm + AT_QAH);  // [4 mtile][2 ks][32]
    uint4* QAl = reinterpret_cast<uint4*>(sm + AT_QAL);
    uint2* KBh = reinterpret_cast<uint2*>(sm + AT_KBH);  // [8 nfrag][2 ks][32]
    uint2* KBl = reinterpret_cast<uint2*>(sm + AT_KBL);
    float* VT  = sm + AT_VT;                             // [32][69]
    float* SS  = sm + AT_SS;                             // [64][68]

    const int tid = threadIdx.x;
    const int wid = tid >> 5, lane = tid & 31;
    const int g = lane >> 2, tg = lane & 3;
    const int m0 = blockIdx.x * NT;

    const int mtile = wid >> 1;          // 0..3 (16 rows)
    const int ms = mtile * 16;
    const int nq = (wid & 1) * 4;        // 4 n-frags of 8
    const int np = (wid & 1) * 2;        // O gemm n-frags

    for (int h = 0; h < NHEAD; h++) {
        __syncthreads();
        // ---- load Q,K as bf16 hi/lo fragments; V transposed fp32 ----
        for (int idx = tid; idx < 2048; idx += 256) {
            const bool isK = idx >= 1024;
            const int i = idx & 1023;
            const int tok = i >> 4;
            const int d   = (i & 15) * 2;
            const float2 v = *reinterpret_cast<const float2*>(
                &g_qkv[(size_t)(m0 + tok) * QKV_N + h * 32 + (isK ? 256 : 0) + d]);
            uint32_t lo; const uint32_t hi = bfsplit2(v.x, v.y, lo);
            const int ks = d >> 4, kin = d & 15;
            if (!isK) {
                const int mt = tok >> 4, r16 = tok & 15;
                const int slot = (mt * 2 + ks) * 32 + (r16 & 7) * 4 + ((kin & 7) >> 1);
                const int reg  = ((kin >> 3) & 1) * 2 + ((r16 >> 3) & 1);
                reinterpret_cast<uint32_t*>(&QAh[slot])[reg] = hi;
                reinterpret_cast<uint32_t*>(&QAl[slot])[reg] = lo;
            } else {
                const int nf = tok >> 3, nr = tok & 7;
                const int slot = (nf * 2 + ks) * 32 + nr * 4 + ((kin & 7) >> 1);
                const int reg  = (kin >> 3) & 1;
                reinterpret_cast<uint32_t*>(&KBh[slot])[reg] = hi;
                reinterpret_cast<uint32_t*>(&KBl[slot])[reg] = lo;
            }
        }
        for (int idx = tid; idx < 2048; idx += 256) {
            const int t = idx >> 5, d = idx & 31;
            VT[d * 69 + t] = g_qkv[(size_t)(m0 + t) * QKV_N + h * 32 + 512 + d];
        }
        for (int i = tid; i < 4096; i += 256)
            SS[(i >> 6) * 68 + (i & 63)] = pos[h * 4096 + i];
        __syncthreads();

        // ---- S = Q K^T, 3-term bf16 ----
        float sacc[4][4];
        #pragma unroll
        for (int j = 0; j < 4; j++)
            #pragma unroll
            for (int z = 0; z < 4; z++) sacc[j][z] = 0.f;

        #pragma unroll
        for (int ks = 0; ks < 2; ks++) {
            const uint4 ah = QAh[(mtile * 2 + ks) * 32 + lane];
            const uint4 al = QAl[(mtile * 2 + ks) * 32 + lane];
            #pragma unroll
            for (int j = 0; j < 4; j++) {
                const uint2 bh = KBh[((nq + j) * 2 + ks) * 32 + lane];
                const uint2 bl = KBl[((nq + j) * 2 + ks) * 32 + lane];
                mma_bf16(sacc[j], ah, bh);
                mma_bf16(sacc[j], al, bh);
                mma_bf16(sacc[j], ah, bl);
            }
        }
        #pragma unroll
        for (int j = 0; j < 4; j++) {
            const int c = (nq + j) * 8 + 2 * tg;
            const int row = ms + g;
            float2* p0 = (float2*)&SS[row * 68 + c];
            float2 v0 = *p0; v0.x += sacc[j][0]; v0.y += sacc[j][1]; *p0 = v0;
            float2* p1 = (float2*)&SS[(row + 8) * 68 + c];
            float2 v1 = *p1; v1.x += sacc[j][2]; v1.y += sacc[j][3]; *p1 = v1;
        }
        __syncthreads();

        // ---- softmax (2 threads per row) ----
        if (tid < 128) {
            const int row = tid >> 1, half = tid & 1;
            float* p = &SS[row * 68 + half * 32];
            float m = -1e30f;
            #pragma unroll 8
            for (int j = 0; j < 32; j++) m = fmaxf(m, p[j]);
            m = fmaxf(m, __shfl_xor_sync(0xFFFFFFFFu, m, 1));
            float s = 0.f;
            #pragma unroll 8
            for (int j = 0; j < 32; j++) { const float e = __expf(p[j] - m); p[j] = e; s += e; }
            s += __shfl_xor_sync(0xFFFFFFFFu, s, 1);
            const float inv = 1.f / s;
            #pragma unroll 8
            for (int j = 0; j < 32; j++) p[j] *= inv;
        }
        __syncthreads();

        // ---- O = S @ V (plain tf32) ----
        float oacc[2][4];
        #pragma unroll
        for (int j = 0; j < 2; j++)
            #pragma unroll
            for (int z = 0; z < 4; z++) oacc[j][z] = 0.f;

        #pragma unroll
        for (int ks = 0; ks < 8; ks++) {
            const int kk = ks * 8;
            const float* Sp = &SS[(ms + g) * 68 + kk + tg];
            const uint32_t a0 = f2tf(Sp[0]),     a1 = f2tf(Sp[8 * 68]);
            const uint32_t a2 = f2tf(Sp[4]),     a3 = f2tf(Sp[8 * 68 + 4]);
            #pragma unroll
            for (int j = 0; j < 2; j++) {
                const float* Vp = &VT[((np + j) * 8 + g) * 69 + kk + tg];
                mma_tf32(oacc[j], a0, a1, a2, a3, f2tf(Vp[0]), f2tf(Vp[4]));
            }
        }
        #pragma unroll
        for (int j = 0; j < 2; j++) {
            const int c = h * 32 + (np + j) * 8 + 2 * tg;
            const int row = ms + g;
            *reinterpret_cast<float2*>(&g_att[(size_t)(m0 + row) * CH + c]) =
                make_float2(oacc[j][0], oacc[j][1]);
            *reinterpret_cast<float2*>(&g_att[(size_t)(m0 + row + 8) * CH + c]) =
                make_float2(oacc[j][2], oacc[j][3]);
        }
    }
}

// ---------------------------------------------------------------------------
// K4: output projection (plain tf32) + bias + residual (validated R6 kernel)
// ---------------------------------------------------------------------------
#define OP_SMEM ((128 + 64) * 68 * 4)

__global__ void __launch_bounds__(256, 3)
outproj_kernel(const float* __restrict__ x, const float* __restrict__ Wo,
               const float* __restrict__ bo, float* __restrict__ out)
{
    extern __shared__ float smf[];
    float* As = smf;
    float* Bs = smf + 128 * 68;

    const int tid = threadIdx.x;
    const int wid = tid >> 5, lane = tid & 31;
    const int g = lane >> 2, tg = lane & 3;
    const int m0 = blockIdx.x * 128;
    const int n0 = blockIdx.y * 64;
    const int wm = (wid & 3) * 32;
    const int wn = (wid >> 2) * 32;

    float acc[2][4][4] = {};

    for (int kc = 0; kc < 4; kc++) {
        const int k0 = kc * 64;
        __syncthreads();
        for (int idx = tid; idx < 128 * 64; idx += 256) {
            const int r = idx >> 6, k = idx & 63;
            As[r * 68 + k] = __uint_as_float(f2tf(g_att[(size_t)(m0 + r) * CH + k0 + k]));
        }
        for (int idx = tid; idx < 64 * 64; idx += 256) {
            const int r = idx >> 6, k = idx & 63;
            Bs[r * 68 + k] = __uint_as_float(f2tf(Wo[(size_t)(n0 + r) * 256 + k0 + k]));
        }
        __syncthreads();
        #pragma unroll
        for (int ks = 0; ks < 8; ks++) {
            const int kk = ks * 8;
            uint32_t a[2][4];
            #pragma unroll
            for (int mi = 0; mi < 2; mi++) {
                const float* Ap = &As[(wm + mi * 16 + g) * 68 + kk + tg];
                a[mi][0] = __float_as_uint(Ap[0]);
                a[mi][1] = __float_as_uint(Ap[8 * 68]);
                a[mi][2] = __float_as_uint(Ap[4]);
                a[mi][3] = __float_as_uint(Ap[8 * 68 + 4]);
            }
            #pragma unroll
            for (int nj = 0; nj < 4; nj++) {
                const float* Bp = &Bs[((wn + nj * 8) + g) * 68 + kk + tg];
                const uint32_t b0 = __float_as_uint(Bp[0]);
                const uint32_t b1 = __float_as_uint(Bp[4]);
                #pragma unroll
                for (int mi = 0; mi < 2; mi++)
                    mma_tf32(acc[mi][nj], a[mi][0], a[mi][1], a[mi][2], a[mi][3], b0, b1);
            }
        }
    }
    #pragma unroll
    for (int mi = 0; mi < 2; mi++) {
        #pragma unroll
        for (int half = 0; half < 2; half++) {
            const int r = wm + mi * 16 + g + half * 8;
            int b, pix; tok2pix(m0 + r, b, pix);
            const size_t base = (size_t)b * CH * IMG * IMG + pix;
            #pragma unroll
            for (int nj = 0; nj < 4; nj++) {
                const int c0 = n0 + wn + nj * 8 + 2 * tg;
                const size_t a0 = base + (size_t)c0 * (IMG * IMG);
                const size_t a1 = a0 + (IMG * IMG);
                out[a0] = acc[mi][nj][half * 2 + 0] + bo[c0]     + x[a0];
                out[a1] = acc[mi][nj][half * 2 + 1] + bo[c0 + 1] + x[a1];
            }
        }
    }
}

// ---------------------------------------------------------------------------
extern "C" void kernel_launch(void* const* d_in, const int* in_sizes, int n_in,
                              void* d_out, int out_size)
{
    const float* x    = (const float*)d_in[0];
    const float* gnw  = (const float*)d_in[1];
    const float* gnb  = (const float*)d_in[2];
    const float* Wq   = (const float*)d_in[3];
    const float* Wk   = (const float*)d_in[4];
    const float* Wv   = (const float*)d_in[5];
    const float* Wo   = (const float*)d_in[6];
    const float* bo   = (const float*)d_in[7];
    const float* pos  = (const float*)d_in[8];
    const float* scl  = (const float*)d_in[9];
    float* out = (float*)d_out;

    cudaFuncSetAttribute(qk_bf16_kernel, cudaFuncAttributeMaxDynamicSharedMemorySize, QK_SMEM);
    cudaFuncSetAttribute(v_gemm_kernel,  cudaFuncAttributeMaxDynamicSharedMemorySize, V_SMEM);
    cudaFuncSetAttribute(attn_kernel,    cudaFuncAttributeMaxDynamicSharedMemorySize, AT_SMEM);
    cudaFuncSetAttribute(outproj_kernel, cudaFuncAttributeMaxDynamicSharedMemorySize, OP_SMEM);

    gn_stats_kernel<<<BATCH * 32, 512>>>(x);
    qk_bf16_kernel<<<dim3(8, NTOK / 128), 256, QK_SMEM>>>(x, gnw, gnb, Wq, Wk, scl);
    v_gemm_kernel<<<dim3(NTOK / 128, 4), 256, V_SMEM>>>(x, gnw, gnb, Wv);
    attn_kernel<<<NTOK / NT, 256, AT_SMEM>>>(pos);
    outproj_kernel<<<dim3(NTOK / 128, 4), 256, OP_SMEM>>>(x, Wo, bo, out);
}

// round 9
// speedup vs baseline: 2.9096x; 1.5137x over previous
#include <cuda_runtime.h>
#include <cuda_bf16.h>
#include <cstdint>

#define BATCH  4
#define CH     256
#define IMG    256
#define WSZ    8
#define NT     64
#define NHEAD  8
#define GN_EPS 1e-5f
#define NTOK   (BATCH * IMG * IMG)          // 262144

// ---- device-global scratch (allocation is banned) ----
__device__ float    g_mean[BATCH * 32];
__device__ float    g_rstd[BATCH * 32];
__device__ uint32_t g_xh[(size_t)NTOK * 128];   // GN(x) bf16x2 hi, [token][128]
__device__ uint32_t g_xl[(size_t)NTOK * 128];   // lo residual
__device__ uint32_t g_wh[1024 * 128];           // Wq|Wk|Wv|Wo rows, bf16x2 hi
__device__ uint32_t g_wl[1024 * 128];
__device__ uint32_t g_qkh[(size_t)NTOK * 256];  // [token][Q 128 pairs | K 128 pairs] hi
__device__ uint32_t g_qkl[(size_t)NTOK * 256];
__device__ float    g_v  [(size_t)NTOK * 256];  // V, tf32-rounded fp32
__device__ uint32_t g_ath[(size_t)NTOK * 128];  // attention out, split bf16
__device__ uint32_t g_atl[(size_t)NTOK * 128];

// ---------------------------------------------------------------------------
// helpers
// ---------------------------------------------------------------------------
__device__ __forceinline__ uint32_t f2tf(float f) {
    uint32_t u; asm("cvt.rna.tf32.f32 %0, %1;" : "=r"(u) : "f"(f)); return u;
}
__device__ __forceinline__ void mma_tf32(float d[4],
    uint32_t a0, uint32_t a1, uint32_t a2, uint32_t a3,
    uint32_t b0, uint32_t b1)
{
    asm("mma.sync.aligned.m16n8k8.row.col.f32.tf32.tf32.f32 "
        "{%0,%1,%2,%3},{%4,%5,%6,%7},{%8,%9},{%0,%1,%2,%3};"
        : "+f"(d[0]), "+f"(d[1]), "+f"(d[2]), "+f"(d[3])
        : "r"(a0), "r"(a1), "r"(a2), "r"(a3), "r"(b0), "r"(b1));
}
__device__ __forceinline__ void mma_bf16(float d[4], uint4 a, uint32_t b0, uint32_t b1)
{
    asm("mma.sync.aligned.m16n8k16.row.col.f32.bf16.bf16.f32 "
        "{%0,%1,%2,%3},{%4,%5,%6,%7},{%8,%9},{%0,%1,%2,%3};"
        : "+f"(d[0]), "+f"(d[1]), "+f"(d[2]), "+f"(d[3])
        : "r"(a.x), "r"(a.y), "r"(a.z), "r"(a.w), "r"(b0), "r"(b1));
}
__device__ __forceinline__ void ldmx4(uint4& d, uint32_t addr) {
    asm volatile("ldmatrix.sync.aligned.m8n8.x4.shared.b16 {%0,%1,%2,%3}, [%4];"
        : "=r"(d.x), "=r"(d.y), "=r"(d.z), "=r"(d.w) : "r"(addr));
}
__device__ __forceinline__ uint32_t s2u(const void* p) {
    uint32_t a;
    asm("{ .reg .u64 t; cvta.to.shared.u64 t, %1; cvt.u32.u64 %0, t; }" : "=r"(a) : "l"(p));
    return a;
}
__device__ __forceinline__ void tok2pix(int m, int& b, int& pix) {
    b = m >> 16;
    const int win = (m >> 6) & 1023;
    const int t   = m & 63;
    pix = ((win >> 5) * WSZ + (t >> 3)) * IMG + (win & 31) * WSZ + (t & 7);
}
__device__ __forceinline__ uint32_t bfsplit2(float a, float b, uint32_t& lo) {
    __nv_bfloat16 ah = __float2bfloat16(a);
    __nv_bfloat16 bh = __float2bfloat16(b);
    __nv_bfloat16 al = __float2bfloat16(a - __bfloat162float(ah));
    __nv_bfloat16 bl = __float2bfloat16(b - __bfloat162float(bh));
    lo = (uint32_t)__bfloat16_as_ushort(al) | ((uint32_t)__bfloat16_as_ushort(bl) << 16);
    return (uint32_t)__bfloat16_as_ushort(ah) | ((uint32_t)__bfloat16_as_ushort(bh) << 16);
}

// ---------------------------------------------------------------------------
// K1: GroupNorm statistics
// ---------------------------------------------------------------------------
__global__ void gn_stats_kernel(const float* __restrict__ x)
{
    const int bg = blockIdx.x;
    const float4* p = reinterpret_cast<const float4*>(x + (size_t)bg * 8 * IMG * IMG);
    const int n4 = (8 * IMG * IMG) / 4;

    float s = 0.f, sq = 0.f;
    for (int i = threadIdx.x; i < n4; i += blockDim.x) {
        float4 v = p[i];
        s  += v.x + v.y + v.z + v.w;
        sq += v.x * v.x + v.y * v.y + v.z * v.z + v.w * v.w;
    }
    for (int o = 16; o; o >>= 1) {
        s  += __shfl_down_sync(0xFFFFFFFFu, s,  o);
        sq += __shfl_down_sync(0xFFFFFFFFu, sq, o);
    }
    __shared__ float ss[32], ssq[32];
    const int w = threadIdx.x >> 5, l = threadIdx.x & 31;
    if (l == 0) { ss[w] = s; ssq[w] = sq; }
    __syncthreads();
    if (w == 0) {
        const int nw = blockDim.x >> 5;
        s  = (l < nw) ? ss[l]  : 0.f;
        sq = (l < nw) ? ssq[l] : 0.f;
        for (int o = 16; o; o >>= 1) {
            s  += __shfl_down_sync(0xFFFFFFFFu, s,  o);
            sq += __shfl_down_sync(0xFFFFFFFFu, sq, o);
        }
        if (l == 0) {
            const float invN = 1.f / (float)(8 * IMG * IMG);
            const float m   = s * invN;
            const float var = sq * invN - m * m;
            g_mean[bg] = m;
            g_rstd[bg] = rsqrtf(var + GN_EPS);
        }
    }
}

// ---------------------------------------------------------------------------
// K0a: split all weights once (Wq|Wk|Wv|Wo -> rows 0..1023)
// ---------------------------------------------------------------------------
__global__ void prep_w_kernel(const float* __restrict__ Wq, const float* __restrict__ Wk,
                              const float* __restrict__ Wv, const float* __restrict__ Wo)
{
    const int idx = blockIdx.x * 256 + threadIdx.x;     // 0..131071
    const int r = idx >> 7, p = idx & 127;
    const float* W = (r < 256) ? Wq : ((r < 512) ? Wk : ((r < 768) ? Wv : Wo));
    const float2 w = *reinterpret_cast<const float2*>(&W[(size_t)(r & 255) * 256 + 2 * p]);
    uint32_t lo; const uint32_t hi = bfsplit2(w.x, w.y, lo);
    g_wh[idx] = hi; g_wl[idx] = lo;
}

// ---------------------------------------------------------------------------
// K0b: GN + bf16 split of x, once, token-major. 128 tokens per block.
// ---------------------------------------------------------------------------
__global__ void prep_x_kernel(const float* __restrict__ x,
                              const float* __restrict__ gnw, const float* __restrict__ gnb)
{
    __shared__ uint32_t Sh[128][17], Sl[128][17];
    const int tid = threadIdx.x;
    const int m0 = blockIdx.x * 128;

    for (int slab = 0; slab < 8; slab++) {
        __syncthreads();
        for (int i = tid; i < 2048; i += 256) {
            const int tok = i & 127, p = i >> 7;        // p 0..15
            const int c = slab * 32 + 2 * p;
            int bb, pix; tok2pix(m0 + tok, bb, pix);
            const size_t base = (size_t)bb * CH * IMG * IMG + pix;
            const float v0 = x[base + (size_t)c * (IMG * IMG)];
            const float v1 = x[base + (size_t)(c + 1) * (IMG * IMG)];
            const float mn = g_mean[bb * 32 + (c >> 3)];
            const float rs = g_rstd[bb * 32 + (c >> 3)];
            const float a = (v0 - mn) * rs * gnw[c]     + gnb[c];
            const float d = (v1 - mn) * rs * gnw[c + 1] + gnb[c + 1];
            uint32_t lo; const uint32_t hi = bfsplit2(a, d, lo);
            Sh[tok][p] = hi; Sl[tok][p] = lo;
        }
        __syncthreads();
        for (int i = tid; i < 2048; i += 256) {
            const int tok = i >> 4, p = i & 15;
            g_xh[(size_t)(m0 + tok) * 128 + slab * 16 + p] = Sh[tok][p];
            g_xl[(size_t)(m0 + tok) * 128 + slab * 16 + p] = Sl[tok][p];
        }
    }
}

// ---------------------------------------------------------------------------
// Shared GEMM mainloop: C[128,64] += A[128,256] * B[64,256]^T, 3-term split-bf16.
// smem: swizzled 128B rows (8 granules, granule ^= row&7). ldmatrix fragments.
// ---------------------------------------------------------------------------
#define SA_H 0
#define SA_L 16384
#define SB_H 32768
#define SB_L 40960
#define GM_SMEM 49152

__device__ __forceinline__ void gemm_mainloop(
    char* smc, uint32_t sbase,
    const uint32_t* __restrict__ Ah_g, const uint32_t* __restrict__ Al_g,
    const uint32_t* __restrict__ Bh_g, const uint32_t* __restrict__ Bl_g,
    float acc[2][4][4])
{
    const int tid = threadIdx.x, wid = tid >> 5, lane = tid & 31;
    const int wm = (wid & 3) * 32, wn = (wid >> 2) * 32;
    const int lrow = lane & 7, seg = lane >> 3;
    const int arow_b = wm + (seg & 1) * 8 + lrow;       // + mi*16
    const int brow_b = wn + (seg >> 1) * 8 + lrow;      // + jj*16
    const int agc = seg >> 1;                            // + 2ks
    const int bgc = seg & 1;                             // + 2ks

    for (int kc = 0; kc < 4; kc++) {
        __syncthreads();
        // fill A (128 rows x 8 granules), hi+lo
        for (int i = tid; i < 1024; i += 256) {
            const int r = i >> 3, gc = i & 7;
            const size_t gs = (size_t)r * 128 + kc * 32 + gc * 4;
            const uint32_t so = r * 128 + ((gc ^ (r & 7)) << 4);
            *reinterpret_cast<uint4*>(smc + SA_H + so) =
                *reinterpret_cast<const uint4*>(Ah_g + gs);
            *reinterpret_cast<uint4*>(smc + SA_L + so) =
                *reinterpret_cast<const uint4*>(Al_g + gs);
        }
        // fill B (64 rows x 8 granules), hi+lo
        for (int i = tid; i < 512; i += 256) {
            const int r = i >> 3, gc = i & 7;
            const size_t gs = (size_t)r * 128 + kc * 32 + gc * 4;
            const uint32_t so = r * 128 + ((gc ^ (r & 7)) << 4);
            *reinterpret_cast<uint4*>(smc + SB_H + so) =
                *reinterpret_cast<const uint4*>(Bh_g + gs);
            *reinterpret_cast<uint4*>(smc + SB_L + so) =
                *reinterpret_cast<const uint4*>(Bl_g + gs);
        }
        __syncthreads();
        #pragma unroll
        for (int ks = 0; ks < 4; ks++) {
            uint4 ah[2], al[2], bh[2], bl[2];
            const int gA = 2 * ks + agc;
            const int gB = 2 * ks + bgc;
            #pragma unroll
            for (int mi = 0; mi < 2; mi++) {
                const int r = arow_b + mi * 16;
                const uint32_t ad = sbase + SA_H + r * 128 + ((gA ^ (r & 7)) << 4);
                ldmx4(ah[mi], ad);
                ldmx4(al[mi], ad + (SA_L - SA_H));
            }
            #pragma unroll
            for (int jj = 0; jj < 2; jj++) {
                const int r = brow_b + jj * 16;
                const uint32_t bd = sbase + SB_H + r * 128 + ((gB ^ (r & 7)) << 4);
                ldmx4(bh[jj], bd);
                ldmx4(bl[jj], bd + (SB_L - SB_H));
            }
            #pragma unroll
            for (int jj = 0; jj < 2; jj++) {
                #pragma unroll
                for (int mi = 0; mi < 2; mi++) {
                    mma_bf16(acc[mi][2 * jj],     ah[mi], bh[jj].x, bh[jj].y);
                    mma_bf16(acc[mi][2 * jj],     al[mi], bh[jj].x, bh[jj].y);
                    mma_bf16(acc[mi][2 * jj],     ah[mi], bl[jj].x, bl[jj].y);
                    mma_bf16(acc[mi][2 * jj + 1], ah[mi], bh[jj].z, bh[jj].w);
                    mma_bf16(acc[mi][2 * jj + 1], al[mi], bh[jj].z, bh[jj].w);
                    mma_bf16(acc[mi][2 * jj + 1], ah[mi], bl[jj].z, bl[jj].w);
                }
            }
        }
    }
}

// ---------------------------------------------------------------------------
// K2: QKV projection. grid (12, NTOK/128). nb 0-3: Q, 4-7: K, 8-11: V.
// ---------------------------------------------------------------------------
__global__ void __launch_bounds__(256, 2)
qkv_gemm_kernel(const float* __restrict__ scale)
{
    extern __shared__ char smc[];
    const uint32_t sbase = s2u(smc);
    const int tid = threadIdx.x, wid = tid >> 5, lane = tid & 31;
    const int nb = blockIdx.x;
    const int m0 = blockIdx.y * 128;

    float acc[2][4][4] = {};
    gemm_mainloop(smc, sbase,
                  g_xh + (size_t)m0 * 128, g_xl + (size_t)m0 * 128,
                  g_wh + (size_t)(nb * 64) * 128, g_wl + (size_t)(nb * 64) * 128,
                  acc);

    const int wm = (wid & 3) * 32, wn = (wid >> 2) * 32;
    const int g = lane >> 2, tg = lane & 3;

    if (nb < 8) {
        const bool isQ = nb < 4;
        const float mul = isQ ? scale[0] : 1.0f;
        const int pbase = (isQ ? 0 : 128) + (nb & 3) * 32 + wn / 2;
        #pragma unroll
        for (int mi = 0; mi < 2; mi++)
            #pragma unroll
            for (int half = 0; half < 2; half++) {
                const int row = m0 + wm + mi * 16 + g + half * 8;
                uint32_t* dh = &g_qkh[(size_t)row * 256 + pbase];
                uint32_t* dl = &g_qkl[(size_t)row * 256 + pbase];
                #pragma unroll
                for (int nj = 0; nj < 4; nj++) {
                    const float d0 = acc[mi][nj][half * 2]     * mul;
                    const float d1 = acc[mi][nj][half * 2 + 1] * mul;
                    uint32_t lo; const uint32_t hi = bfsplit2(d0, d1, lo);
                    dh[nj * 4 + tg] = hi;
                    dl[nj * 4 + tg] = lo;
                }
            }
    } else {
        const int cbase = (nb & 3) * 64 + wn;
        #pragma unroll
        for (int mi = 0; mi < 2; mi++)
            #pragma unroll
            for (int half = 0; half < 2; half++) {
                const int row = m0 + wm + mi * 16 + g + half * 8;
                #pragma unroll
                for (int nj = 0; nj < 4; nj++) {
                    const int c = cbase + nj * 8 + 2 * tg;
                    *reinterpret_cast<float2*>(&g_v[(size_t)row * 256 + c]) = make_float2(
                        __uint_as_float(f2tf(acc[mi][nj][half * 2])),
                        __uint_as_float(f2tf(acc[mi][nj][half * 2 + 1])));
                }
            }
    }
}

// ---------------------------------------------------------------------------
// K3: per-window attention. S: 3-term bf16 via ldmatrix; S·V: tf32 (validated).
// smem bytes: Qh 5120 | Ql 5120 | Kh 5120 | Kl 5120 | VT [32][69]f | SS [64][68]f
// rows of Q/K: 16 uint32 used, stride 20 uint32 (80B) -> conflict-free ldmatrix.
// ---------------------------------------------------------------------------
#define AQ_H 0
#define AQ_L 5120
#define AK_H 10240
#define AK_L 15360
#define AVT  20480
#define ASS  29312
#define AT_SMEM 46720

__global__ void __launch_bounds__(256)
attn_kernel(const float* __restrict__ pos)
{
    extern __shared__ char smc[];
    const uint32_t sbase = s2u(smc);
    float* VT = reinterpret_cast<float*>(smc + AVT);   // [32][69]
    float* SS = reinterpret_cast<float*>(smc + ASS);   // [64][68]

    const int tid = threadIdx.x;
    const int wid = tid >> 5, lane = tid & 31;
    const int g = lane >> 2, tg = lane & 3;
    const int m0 = blockIdx.x * NT;

    const int mtile = wid >> 1;
    const int ms = mtile * 16;
    const int nq = (wid & 1) * 4;        // 4 n-frags for S
    const int np = (wid & 1) * 2;        // 2 n-frags for O
    const int lrow = lane & 7, seg = lane >> 3;

    for (int h = 0; h < NHEAD; h++) {
        __syncthreads();
        // ---- fills: Q/K split pairs (pure copies), V (pre-rounded), pos ----
        for (int i = tid; i < 512; i += 256) {
            const int isK = i >> 8;
            const int r = (i >> 2) & 63, gc = i & 3;
            const size_t gs = (size_t)(m0 + r) * 256 + (isK ? 128 : 0) + h * 16 + gc * 4;
            const uint32_t so = r * 80 + gc * 16;
            *reinterpret_cast<uint4*>(smc + (isK ? AK_H : AQ_H) + so) =
                *reinterpret_cast<const uint4*>(g_qkh + gs);
            *reinterpret_cast<uint4*>(smc + (isK ? AK_L : AQ_L) + so) =
                *reinterpret_cast<const uint4*>(g_qkl + gs);
        }
        for (int idx = tid; idx < 2048; idx += 256) {
            const int t = idx >> 5, d = idx & 31;
            VT[d * 69 + t] = g_v[(size_t)(m0 + t) * 256 + h * 32 + d];
        }
        for (int i = tid; i < 4096; i += 256)
            SS[(i >> 6) * 68 + (i & 63)] = pos[h * 4096 + i];
        __syncthreads();

        // ---- S = Q K^T, 3-term bf16 via ldmatrix ----
        float sacc[4][4];
        #pragma unroll
        for (int j = 0; j < 4; j++)
            #pragma unroll
            for (int z = 0; z < 4; z++) sacc[j][z] = 0.f;

        #pragma unroll
        for (int ks = 0; ks < 2; ks++) {
            const int gA = 2 * ks + (seg >> 1);
            const int gB = 2 * ks + (seg & 1);
            const int qrow = ms + (seg & 1) * 8 + lrow;
            uint4 qh, ql;
            ldmx4(qh, sbase + AQ_H + qrow * 80 + gA * 16);
            ldmx4(ql, sbase + AQ_L + qrow * 80 + gA * 16);
            #pragma unroll
            for (int jj = 0; jj < 2; jj++) {
                const int krow = (nq + 2 * jj) * 8 + (seg >> 1) * 8 + lrow;
                uint4 kh, kl;
                ldmx4(kh, sbase + AK_H + krow * 80 + gB * 16);
                ldmx4(kl, sbase + AK_L + krow * 80 + gB * 16);
                mma_bf16(sacc[2 * jj],     qh, kh.x, kh.y);
                mma_bf16(sacc[2 * jj],     ql, kh.x, kh.y);
                mma_bf16(sacc[2 * jj],     qh, kl.x, kl.y);
                mma_bf16(sacc[2 * jj + 1], qh, kh.z, kh.w);
                mma_bf16(sacc[2 * jj + 1], ql, kh.z, kh.w);
                mma_bf16(sacc[2 * jj + 1], qh, kl.z, kl.w);
            }
        }
        #pragma unroll
        for (int j = 0; j < 4; j++) {
            const int c = (nq + j) * 8 + 2 * tg;
            const int row = ms + g;
            float2* p0 = (float2*)&SS[row * 68 + c];
            float2 v0 = *p0; v0.x += sacc[j][0]; v0.y += sacc[j][1]; *p0 = v0;
            float2* p1 = (float2*)&SS[(row + 8) * 68 + c];
            float2 v1 = *p1; v1.x += sacc[j][2]; v1.y += sacc[j][3]; *p1 = v1;
        }
        __syncthreads();

        // ---- softmax (2 threads per row) ----
        if (tid < 128) {
            const int row = tid >> 1, half = tid & 1;
            float* p = &SS[row * 68 + half * 32];
            float m = -1e30f;
            #pragma unroll 8
            for (int j = 0; j < 32; j++) m = fmaxf(m, p[j]);
            m = fmaxf(m, __shfl_xor_sync(0xFFFFFFFFu, m, 1));
            float s = 0.f;
            #pragma unroll 8
            for (int j = 0; j < 32; j++) { const float e = __expf(p[j] - m); p[j] = e; s += e; }
            s += __shfl_xor_sync(0xFFFFFFFFu, s, 1);
            const float inv = 1.f / s;
            #pragma unroll 8
            for (int j = 0; j < 32; j++) p[j] *= inv;
        }
        __syncthreads();

        // ---- O = S @ V (plain tf32, validated) ----
        float oacc[2][4];
        #pragma unroll
        for (int j = 0; j < 2; j++)
            #pragma unroll
            for (int z = 0; z < 4; z++) oacc[j][z] = 0.f;

        #pragma unroll
        for (int ks = 0; ks < 8; ks++) {
            const int kk = ks * 8;
            const float* Sp = &SS[(ms + g) * 68 + kk + tg];
            const uint32_t a0 = f2tf(Sp[0]),     a1 = f2tf(Sp[8 * 68]);
            const uint32_t a2 = f2tf(Sp[4]),     a3 = f2tf(Sp[8 * 68 + 4]);
            #pragma unroll
            for (int j = 0; j < 2; j++) {
                const float* Vp = &VT[((np + j) * 8 + g) * 69 + kk + tg];
                mma_tf32(oacc[j], a0, a1, a2, a3,
                         __float_as_uint(Vp[0]), __float_as_uint(Vp[4]));
            }
        }
        // write attention output pre-split for outproj
        #pragma unroll
        for (int j = 0; j < 2; j++) {
            const int pb = h * 16 + (np + j) * 4 + tg;
            #pragma unroll
            for (int half = 0; half < 2; half++) {
                const int row = ms + g + half * 8;
                uint32_t lo;
                const uint32_t hi = bfsplit2(oacc[j][half * 2], oacc[j][half * 2 + 1], lo);
                g_ath[(size_t)(m0 + row) * 128 + pb] = hi;
                g_atl[(size_t)(m0 + row) * 128 + pb] = lo;
            }
        }
    }
}

// ---------------------------------------------------------------------------
// K4: output projection (3-term bf16) + bias + residual scatter.
// grid (4, NTOK/128).
// ---------------------------------------------------------------------------
__global__ void __launch_bounds__(256, 2)
outproj_gemm_kernel(const float* __restrict__ x, const float* __restrict__ bo,
                    float* __restrict__ out)
{
    extern __shared__ char smc[];
    const uint32_t sbase = s2u(smc);
    const int tid = threadIdx.x, wid = tid >> 5, lane = tid & 31;
    const int nb = blockIdx.x;           // 0..3
    const int m0 = blockIdx.y * 128;

    float acc[2][4][4] = {};
    gemm_mainloop(smc, sbase,
                  g_ath + (size_t)m0 * 128, g_atl + (size_t)m0 * 128,
                  g_wh + (size_t)(768 + nb * 64) * 128,
                  g_wl + (size_t)(768 + nb * 64) * 128,
                  acc);

    const int wm = (wid & 3) * 32, wn = (wid >> 2) * 32;
    const int g = lane >> 2, tg = lane & 3;
    const int n0 = nb * 64;
    #pragma unroll
    for (int mi = 0; mi < 2; mi++) {
        #pragma unroll
        for (int half = 0; half < 2; half++) {
            const int r = wm + mi * 16 + g + half * 8;
            int b, pix; tok2pix(m0 + r, b, pix);
            const size_t base = (size_t)b * CH * IMG * IMG + pix;
            #pragma unroll
            for (int nj = 0; nj < 4; nj++) {
                const int c0 = n0 + wn + nj * 8 + 2 * tg;
                const size_t a0 = base + (size_t)c0 * (IMG * IMG);
                const size_t a1 = a0 + (IMG * IMG);
                out[a0] = acc[mi][nj][half * 2 + 0] + bo[c0]     + x[a0];
                out[a1] = acc[mi][nj][half * 2 + 1] + bo[c0 + 1] + x[a1];
            }
        }
    }
}

// ---------------------------------------------------------------------------
extern "C" void kernel_launch(void* const* d_in, const int* in_sizes, int n_in,
                              void* d_out, int out_size)
{
    const float* x    = (const float*)d_in[0];
    const float* gnw  = (const float*)d_in[1];
    const float* gnb  = (const float*)d_in[2];
    const float* Wq   = (const float*)d_in[3];
    const float* Wk   = (const float*)d_in[4];
    const float* Wv   = (const float*)d_in[5];
    const float* Wo   = (const float*)d_in[6];
    const float* bo   = (const float*)d_in[7];
    const float* pos  = (const float*)d_in[8];
    const float* scl  = (const float*)d_in[9];
    float* out = (float*)d_out;

    cudaFuncSetAttribute(qkv_gemm_kernel,     cudaFuncAttributeMaxDynamicSharedMemorySize, GM_SMEM);
    cudaFuncSetAttribute(outproj_gemm_kernel, cudaFuncAttributeMaxDynamicSharedMemorySize, GM_SMEM);
    cudaFuncSetAttribute(attn_kernel,         cudaFuncAttributeMaxDynamicSharedMemorySize, AT_SMEM);

    gn_stats_kernel<<<BATCH * 32, 512>>>(x);
    prep_w_kernel<<<512, 256>>>(Wq, Wk, Wv, Wo);
    prep_x_kernel<<<NTOK / 128, 256>>>(x, gnw, gnb);
    qkv_gemm_kernel<<<dim3(12, NTOK / 128), 256, GM_SMEM>>>(scl);
    attn_kernel<<<NTOK / NT, 256, AT_SMEM>>>(pos);
    outproj_gemm_kernel<<<dim3(4, NTOK / 128), 256, GM_SMEM>>>(x, bo, out);
}

// round 10
// speedup vs baseline: 4.2622x; 1.4649x over previous
#include <cuda_runtime.h>
#include <cuda_bf16.h>
#include <cstdint>

#define BATCH  4
#define CH     256
#define IMG    256
#define WSZ    8
#define NT     64
#define NHEAD  8
#define GN_EPS 1e-5f
#define NTOK   (BATCH * IMG * IMG)          // 262144

// ---- device-global scratch (allocation is banned) ----
__device__ float    g_mean[BATCH * 32];
__device__ float    g_rstd[BATCH * 32];
__device__ uint32_t g_xh[(size_t)NTOK * 128];   // GN(x) bf16x2 hi, [token][128]
__device__ uint32_t g_xl[(size_t)NTOK * 128];   // lo residual
__device__ uint32_t g_wh[1024 * 128];           // Wq|Wk|Wv|Wo rows, bf16x2 hi
__device__ uint32_t g_wl[1024 * 128];
__device__ uint32_t g_qkh[(size_t)NTOK * 256];  // [token][Q 128 pairs | K 128 pairs] hi
__device__ uint32_t g_qkl[(size_t)NTOK * 256];
__device__ float    g_v  [(size_t)NTOK * 256];  // V, tf32-rounded fp32
__device__ uint32_t g_ath[(size_t)NTOK * 128];  // attention out, split bf16
__device__ uint32_t g_atl[(size_t)NTOK * 128];

// ---------------------------------------------------------------------------
// helpers
// ---------------------------------------------------------------------------
__device__ __forceinline__ uint32_t f2tf(float f) {
    uint32_t u; asm("cvt.rna.tf32.f32 %0, %1;" : "=r"(u) : "f"(f)); return u;
}
__device__ __forceinline__ void mma_tf32(float d[4],
    uint32_t a0, uint32_t a1, uint32_t a2, uint32_t a3,
    uint32_t b0, uint32_t b1)
{
    asm("mma.sync.aligned.m16n8k8.row.col.f32.tf32.tf32.f32 "
        "{%0,%1,%2,%3},{%4,%5,%6,%7},{%8,%9},{%0,%1,%2,%3};"
        : "+f"(d[0]), "+f"(d[1]), "+f"(d[2]), "+f"(d[3])
        : "r"(a0), "r"(a1), "r"(a2), "r"(a3), "r"(b0), "r"(b1));
}
__device__ __forceinline__ void mma_bf16(float d[4], uint4 a, uint32_t b0, uint32_t b1)
{
    asm("mma.sync.aligned.m16n8k16.row.col.f32.bf16.bf16.f32 "
        "{%0,%1,%2,%3},{%4,%5,%6,%7},{%8,%9},{%0,%1,%2,%3};"
        : "+f"(d[0]), "+f"(d[1]), "+f"(d[2]), "+f"(d[3])
        : "r"(a.x), "r"(a.y), "r"(a.z), "r"(a.w), "r"(b0), "r"(b1));
}
__device__ __forceinline__ void ldmx4(uint4& d, uint32_t addr) {
    asm volatile("ldmatrix.sync.aligned.m8n8.x4.shared.b16 {%0,%1,%2,%3}, [%4];"
        : "=r"(d.x), "=r"(d.y), "=r"(d.z), "=r"(d.w) : "r"(addr));
}
__device__ __forceinline__ uint32_t s2u(const void* p) {
    uint32_t a;
    asm("{ .reg .u64 t; cvta.to.shared.u64 t, %1; cvt.u32.u64 %0, t; }" : "=r"(a) : "l"(p));
    return a;
}
__device__ __forceinline__ void cpa16(uint32_t saddr, const void* gptr) {
    asm volatile("cp.async.cg.shared.global [%0], [%1], 16;" :: "r"(saddr), "l"(gptr));
}
__device__ __forceinline__ void tok2pix(int m, int& b, int& pix) {
    b = m >> 16;
    const int win = (m >> 6) & 1023;
    const int t   = m & 63;
    pix = ((win >> 5) * WSZ + (t >> 3)) * IMG + (win & 31) * WSZ + (t & 7);
}
__device__ __forceinline__ uint32_t bfsplit2(float a, float b, uint32_t& lo) {
    __nv_bfloat16 ah = __float2bfloat16(a);
    __nv_bfloat16 bh = __float2bfloat16(b);
    __nv_bfloat16 al = __float2bfloat16(a - __bfloat162float(ah));
    __nv_bfloat16 bl = __float2bfloat16(b - __bfloat162float(bh));
    lo = (uint32_t)__bfloat16_as_ushort(al) | ((uint32_t)__bfloat16_as_ushort(bl) << 16);
    return (uint32_t)__bfloat16_as_ushort(ah) | ((uint32_t)__bfloat16_as_ushort(bh) << 16);
}

// ---------------------------------------------------------------------------
// K1: GroupNorm statistics
// ---------------------------------------------------------------------------
__global__ void gn_stats_kernel(const float* __restrict__ x)
{
    const int bg = blockIdx.x;
    const float4* p = reinterpret_cast<const float4*>(x + (size_t)bg * 8 * IMG * IMG);
    const int n4 = (8 * IMG * IMG) / 4;

    float s = 0.f, sq = 0.f;
    for (int i = threadIdx.x; i < n4; i += blockDim.x) {
        float4 v = p[i];
        s  += v.x + v.y + v.z + v.w;
        sq += v.x * v.x + v.y * v.y + v.z * v.z + v.w * v.w;
    }
    for (int o = 16; o; o >>= 1) {
        s  += __shfl_down_sync(0xFFFFFFFFu, s,  o);
        sq += __shfl_down_sync(0xFFFFFFFFu, sq, o);
    }
    __shared__ float ss[32], ssq[32];
    const int w = threadIdx.x >> 5, l = threadIdx.x & 31;
    if (l == 0) { ss[w] = s; ssq[w] = sq; }
    __syncthreads();
    if (w == 0) {
        const int nw = blockDim.x >> 5;
        s  = (l < nw) ? ss[l]  : 0.f;
        sq = (l < nw) ? ssq[l] : 0.f;
        for (int o = 16; o; o >>= 1) {
            s  += __shfl_down_sync(0xFFFFFFFFu, s,  o);
            sq += __shfl_down_sync(0xFFFFFFFFu, sq, o);
        }
        if (l == 0) {
            const float invN = 1.f / (float)(8 * IMG * IMG);
            const float m   = s * invN;
            const float var = sq * invN - m * m;
            g_mean[bg] = m;
            g_rstd[bg] = rsqrtf(var + GN_EPS);
        }
    }
}

// ---------------------------------------------------------------------------
// K0a: split all weights once (Wq|Wk|Wv|Wo -> rows 0..1023)
// ---------------------------------------------------------------------------
__global__ void prep_w_kernel(const float* __restrict__ Wq, const float* __restrict__ Wk,
                              const float* __restrict__ Wv, const float* __restrict__ Wo)
{
    const int idx = blockIdx.x * 256 + threadIdx.x;     // 0..131071
    const int r = idx >> 7, p = idx & 127;
    const float* W = (r < 256) ? Wq : ((r < 512) ? Wk : ((r < 768) ? Wv : Wo));
    const float2 w = *reinterpret_cast<const float2*>(&W[(size_t)(r & 255) * 256 + 2 * p]);
    uint32_t lo; const uint32_t hi = bfsplit2(w.x, w.y, lo);
    g_wh[idx] = hi; g_wl[idx] = lo;
}

// ---------------------------------------------------------------------------
// K0b: GN + bf16 split of x, once, token-major. 128 tokens per block.
// ---------------------------------------------------------------------------
__global__ void prep_x_kernel(const float* __restrict__ x,
                              const float* __restrict__ gnw, const float* __restrict__ gnb)
{
    __shared__ uint32_t Sh[128][17], Sl[128][17];
    const int tid = threadIdx.x;
    const int m0 = blockIdx.x * 128;

    for (int slab = 0; slab < 8; slab++) {
        __syncthreads();
        for (int i = tid; i < 2048; i += 256) {
            const int tok = i & 127, p = i >> 7;        // p 0..15
            const int c = slab * 32 + 2 * p;
            int bb, pix; tok2pix(m0 + tok, bb, pix);
            const size_t base = (size_t)bb * CH * IMG * IMG + pix;
            const float v0 = x[base + (size_t)c * (IMG * IMG)];
            const float v1 = x[base + (size_t)(c + 1) * (IMG * IMG)];
            const float mn = g_mean[bb * 32 + (c >> 3)];
            const float rs = g_rstd[bb * 32 + (c >> 3)];
            const float a = (v0 - mn) * rs * gnw[c]     + gnb[c];
            const float d = (v1 - mn) * rs * gnw[c + 1] + gnb[c + 1];
            uint32_t lo; const uint32_t hi = bfsplit2(a, d, lo);
            Sh[tok][p] = hi; Sl[tok][p] = lo;
        }
        __syncthreads();
        for (int i = tid; i < 2048; i += 256) {
            const int tok = i >> 4, p = i & 15;
            g_xh[(size_t)(m0 + tok) * 128 + slab * 16 + p] = Sh[tok][p];
            g_xl[(size_t)(m0 + tok) * 128 + slab * 16 + p] = Sl[tok][p];
        }
    }
}

// ---------------------------------------------------------------------------
// Shared GEMM mainloop: C[128,128] += A[128,256] * B[128,256]^T, 3-term bf16.
// 64KB smem, cp.async fills, ldmatrix fragments, warp tile 32m x 64n.
// ---------------------------------------------------------------------------
#define SA_H 0
#define SA_L 16384
#define SB_H 32768
#define SB_L 49152
#define GM_SMEM 65536

__device__ __forceinline__ void gemm_mainloop128(
    uint32_t sbase,
    const uint32_t* __restrict__ Ah_g, const uint32_t* __restrict__ Al_g,
    const uint32_t* __restrict__ Bh_g, const uint32_t* __restrict__ Bl_g,
    float acc[2][8][4])
{
    const int tid = threadIdx.x, wid = tid >> 5, lane = tid & 31;
    const int wm = (wid & 3) * 32, wn = (wid >> 2) * 64;
    const int lrow = lane & 7, seg = lane >> 3;
    const int arow_b = wm + (seg & 1) * 8 + lrow;        // + mi*16
    const int brow_b = wn + (seg >> 1) * 8 + lrow;       // + half*32 + jj*16
    const int agc = seg >> 1;                            // + 2ks
    const int bgc = seg & 1;                             // + 2ks

    for (int kc = 0; kc < 4; kc++) {
        __syncthreads();
        // ---- cp.async fills: A(128 rows) + B(128 rows), hi+lo, 16B granules ----
        #pragma unroll
        for (int i = tid; i < 1024; i += 256) {
            const int r = i >> 3, gc = i & 7;
            const size_t gs = (size_t)r * 128 + kc * 32 + gc * 4;
            const uint32_t so = r * 128 + ((gc ^ (r & 7)) << 4);
            cpa16(sbase + SA_H + so, Ah_g + gs);
            cpa16(sbase + SA_L + so, Al_g + gs);
            cpa16(sbase + SB_H + so, Bh_g + gs);
            cpa16(sbase + SB_L + so, Bl_g + gs);
        }
        asm volatile("cp.async.commit_group;");
        asm volatile("cp.async.wait_group 0;" ::: "memory");
        __syncthreads();
        // ---- compute: 4 k16 steps ----
        #pragma unroll
        for (int ks = 0; ks < 4; ks++) {
            const int gA = 2 * ks + agc;
            const int gB = 2 * ks + bgc;
            uint4 ah[2], al[2];
            #pragma unroll
            for (int mi = 0; mi < 2; mi++) {
                const int r = arow_b + mi * 16;
                const uint32_t ad = sbase + SA_H + r * 128 + ((gA ^ (r & 7)) << 4);
                ldmx4(ah[mi], ad);
                ldmx4(al[mi], ad + (SA_L - SA_H));
            }
            #pragma unroll
            for (int half = 0; half < 2; half++) {
                uint4 bh[2], bl[2];
                #pragma unroll
                for (int jj = 0; jj < 2; jj++) {
                    const int r = brow_b + half * 32 + jj * 16;
                    const uint32_t bd = sbase + SB_H + r * 128 + ((gB ^ (r & 7)) << 4);
                    ldmx4(bh[jj], bd);
                    ldmx4(bl[jj], bd + (SB_L - SB_H));
                }
                #pragma unroll
                for (int jj = 0; jj < 2; jj++) {
                    const int n0 = half * 4 + 2 * jj;
                    #pragma unroll
                    for (int mi = 0; mi < 2; mi++) {
                        mma_bf16(acc[mi][n0],     ah[mi], bh[jj].x, bh[jj].y);
                        mma_bf16(acc[mi][n0],     al[mi], bh[jj].x, bh[jj].y);
                        mma_bf16(acc[mi][n0],     ah[mi], bl[jj].x, bl[jj].y);
                        mma_bf16(acc[mi][n0 + 1], ah[mi], bh[jj].z, bh[jj].w);
                        mma_bf16(acc[mi][n0 + 1], al[mi], bh[jj].z, bh[jj].w);
                        mma_bf16(acc[mi][n0 + 1], ah[mi], bl[jj].z, bl[jj].w);
                    }
                }
            }
        }
    }
}

// ---------------------------------------------------------------------------
// K2: QKV projection. grid (6, NTOK/128). nb 0-1: Q, 2-3: K, 4-5: V.
// ---------------------------------------------------------------------------
__global__ void __launch_bounds__(256, 2)
qkv_gemm_kernel(const float* __restrict__ scale)
{
    extern __shared__ char smc[];
    const uint32_t sbase = s2u(smc);
    const int tid = threadIdx.x, wid = tid >> 5, lane = tid & 31;
    const int nb = blockIdx.x;
    const int m0 = blockIdx.y * 128;

    float acc[2][8][4] = {};
    gemm_mainloop128(sbase,
                     g_xh + (size_t)m0 * 128, g_xl + (size_t)m0 * 128,
                     g_wh + (size_t)(nb * 128) * 128, g_wl + (size_t)(nb * 128) * 128,
                     acc);

    const int wm = (wid & 3) * 32, wn = (wid >> 2) * 64;
    const int g = lane >> 2, tg = lane & 3;

    if (nb < 4) {
        const bool isQ = nb < 2;
        const float mul = isQ ? scale[0] : 1.0f;
        const int pbase = (isQ ? 0 : 128) + (nb & 1) * 64 + wn / 2;
        #pragma unroll
        for (int mi = 0; mi < 2; mi++)
            #pragma unroll
            for (int half = 0; half < 2; half++) {
                const int row = m0 + wm + mi * 16 + g + half * 8;
                uint32_t* dh = &g_qkh[(size_t)row * 256 + pbase];
                uint32_t* dl = &g_qkl[(size_t)row * 256 + pbase];
                #pragma unroll
                for (int nj = 0; nj < 8; nj++) {
                    const float d0 = acc[mi][nj][half * 2]     * mul;
                    const float d1 = acc[mi][nj][half * 2 + 1] * mul;
                    uint32_t lo; const uint32_t hi = bfsplit2(d0, d1, lo);
                    dh[nj * 4 + tg] = hi;
                    dl[nj * 4 + tg] = lo;
                }
            }
    } else {
        const int cbase = (nb & 1) * 128 + wn;
        #pragma unroll
        for (int mi = 0; mi < 2; mi++)
            #pragma unroll
            for (int half = 0; half < 2; half++) {
                const int row = m0 + wm + mi * 16 + g + half * 8;
                #pragma unroll
                for (int nj = 0; nj < 8; nj++) {
                    const int c = cbase + nj * 8 + 2 * tg;
                    *reinterpret_cast<float2*>(&g_v[(size_t)row * 256 + c]) = make_float2(
                        __uint_as_float(f2tf(acc[mi][nj][half * 2])),
                        __uint_as_float(f2tf(acc[mi][nj][half * 2 + 1])));
                }
            }
    }
}

// ---------------------------------------------------------------------------
// K3: per-window attention (unchanged from R9; verified).
// ---------------------------------------------------------------------------
#define AQ_H 0
#define AQ_L 5120
#define AK_H 10240
#define AK_L 15360
#define AVT  20480
#define ASS  29312
#define AT_SMEM 46720

__global__ void __launch_bounds__(256)
attn_kernel(const float* __restrict__ pos)
{
    extern __shared__ char smc[];
    const uint32_t sbase = s2u(smc);
    float* VT = reinterpret_cast<float*>(smc + AVT);   // [32][69]
    float* SS = reinterpret_cast<float*>(smc + ASS);   // [64][68]

    const int tid = threadIdx.x;
    const int wid = tid >> 5, lane = tid & 31;
    const int g = lane >> 2, tg = lane & 3;
    const int m0 = blockIdx.x * NT;

    const int mtile = wid >> 1;
    const int ms = mtile * 16;
    const int nq = (wid & 1) * 4;
    const int np = (wid & 1) * 2;
    const int lrow = lane & 7, seg = lane >> 3;

    for (int h = 0; h < NHEAD; h++) {
        __syncthreads();
        for (int i = tid; i < 512; i += 256) {
            const int isK = i >> 8;
            const int r = (i >> 2) & 63, gc = i & 3;
            const size_t gs = (size_t)(m0 + r) * 256 + (isK ? 128 : 0) + h * 16 + gc * 4;
            const uint32_t so = r * 80 + gc * 16;
            *reinterpret_cast<uint4*>(smc + (isK ? AK_H : AQ_H) + so) =
                *reinterpret_cast<const uint4*>(g_qkh + gs);
            *reinterpret_cast<uint4*>(smc + (isK ? AK_L : AQ_L) + so) =
                *reinterpret_cast<const uint4*>(g_qkl + gs);
        }
        for (int idx = tid; idx < 2048; idx += 256) {
            const int t = idx >> 5, d = idx & 31;
            VT[d * 69 + t] = g_v[(size_t)(m0 + t) * 256 + h * 32 + d];
        }
        for (int i = tid; i < 4096; i += 256)
            SS[(i >> 6) * 68 + (i & 63)] = pos[h * 4096 + i];
        __syncthreads();

        float sacc[4][4];
        #pragma unroll
        for (int j = 0; j < 4; j++)
            #pragma unroll
            for (int z = 0; z < 4; z++) sacc[j][z] = 0.f;

        #pragma unroll
        for (int ks = 0; ks < 2; ks++) {
            const int gA = 2 * ks + (seg >> 1);
            const int gB = 2 * ks + (seg & 1);
            const int qrow = ms + (seg & 1) * 8 + lrow;
            uint4 qh, ql;
            ldmx4(qh, sbase + AQ_H + qrow * 80 + gA * 16);
            ldmx4(ql, sbase + AQ_L + qrow * 80 + gA * 16);
            #pragma unroll
            for (int jj = 0; jj < 2; jj++) {
                const int krow = (nq + 2 * jj) * 8 + (seg >> 1) * 8 + lrow;
                uint4 kh, kl;
                ldmx4(kh, sbase + AK_H + krow * 80 + gB * 16);
                ldmx4(kl, sbase + AK_L + krow * 80 + gB * 16);
                mma_bf16(sacc[2 * jj],     qh, kh.x, kh.y);
                mma_bf16(sacc[2 * jj],     ql, kh.x, kh.y);
                mma_bf16(sacc[2 * jj],     qh, kl.x, kl.y);
                mma_bf16(sacc[2 * jj + 1], qh, kh.z, kh.w);
                mma_bf16(sacc[2 * jj + 1], ql, kh.z, kh.w);
                mma_bf16(sacc[2 * jj + 1], qh, kl.z, kl.w);
            }
        }
        #pragma unroll
        for (int j = 0; j < 4; j++) {
            const int c = (nq + j) * 8 + 2 * tg;
            const int row = ms + g;
            float2* p0 = (float2*)&SS[row * 68 + c];
            float2 v0 = *p0; v0.x += sacc[j][0]; v0.y += sacc[j][1]; *p0 = v0;
            float2* p1 = (float2*)&SS[(row + 8) * 68 + c];
            float2 v1 = *p1; v1.x += sacc[j][2]; v1.y += sacc[j][3]; *p1 = v1;
        }
        __syncthreads();

        if (tid < 128) {
            const int row = tid >> 1, half = tid & 1;
            float* p = &SS[row * 68 + half * 32];
            float m = -1e30f;
            #pragma unroll 8
            for (int j = 0; j < 32; j++) m = fmaxf(m, p[j]);
            m = fmaxf(m, __shfl_xor_sync(0xFFFFFFFFu, m, 1));
            float s = 0.f;
            #pragma unroll 8
            for (int j = 0; j < 32; j++) { const float e = __expf(p[j] - m); p[j] = e; s += e; }
            s += __shfl_xor_sync(0xFFFFFFFFu, s, 1);
            const float inv = 1.f / s;
            #pragma unroll 8
            for (int j = 0; j < 32; j++) p[j] *= inv;
        }
        __syncthreads();

        float oacc[2][4];
        #pragma unroll
        for (int j = 0; j < 2; j++)
            #pragma unroll
            for (int z = 0; z < 4; z++) oacc[j][z] = 0.f;

        #pragma unroll
        for (int ks = 0; ks < 8; ks++) {
            const int kk = ks * 8;
            const float* Sp = &SS[(ms + g) * 68 + kk + tg];
            const uint32_t a0 = f2tf(Sp[0]),     a1 = f2tf(Sp[8 * 68]);
            const uint32_t a2 = f2tf(Sp[4]),     a3 = f2tf(Sp[8 * 68 + 4]);
            #pragma unroll
            for (int j = 0; j < 2; j++) {
                const float* Vp = &VT[((np + j) * 8 + g) * 69 + kk + tg];
                mma_tf32(oacc[j], a0, a1, a2, a3,
                         __float_as_uint(Vp[0]), __float_as_uint(Vp[4]));
            }
        }
        #pragma unroll
        for (int j = 0; j < 2; j++) {
            const int pb = h * 16 + (np + j) * 4 + tg;
            #pragma unroll
            for (int half = 0; half < 2; half++) {
                const int row = ms + g + half * 8;
                uint32_t lo;
                const uint32_t hi = bfsplit2(oacc[j][half * 2], oacc[j][half * 2 + 1], lo);
                g_ath[(size_t)(m0 + row) * 128 + pb] = hi;
                g_atl[(size_t)(m0 + row) * 128 + pb] = lo;
            }
        }
    }
}

// ---------------------------------------------------------------------------
// K4: output projection (3-term bf16, 128x128 tile) + bias + residual.
// grid (2, NTOK/128).
// ---------------------------------------------------------------------------
__global__ void __launch_bounds__(256, 2)
outproj_gemm_kernel(const float* __restrict__ x, const float* __restrict__ bo,
                    float* __restrict__ out)
{
    extern __shared__ char smc[];
    const uint32_t sbase = s2u(smc);
    const int tid = threadIdx.x, wid = tid >> 5, lane = tid & 31;
    const int nb = blockIdx.x;           // 0..1
    const int m0 = blockIdx.y * 128;

    float acc[2][8][4] = {};
    gemm_mainloop128(sbase,
                     g_ath + (size_t)m0 * 128, g_atl + (size_t)m0 * 128,
                     g_wh + (size_t)(768 + nb * 128) * 128,
                     g_wl + (size_t)(768 + nb * 128) * 128,
                     acc);

    const int wm = (wid & 3) * 32, wn = (wid >> 2) * 64;
    const int g = lane >> 2, tg = lane & 3;
    const int n0 = nb * 128;
    #pragma unroll
    for (int mi = 0; mi < 2; mi++) {
        #pragma unroll
        for (int half = 0; half < 2; half++) {
            const int r = wm + mi * 16 + g + half * 8;
            int b, pix; tok2pix(m0 + r, b, pix);
            const size_t base = (size_t)b * CH * IMG * IMG + pix;
            #pragma unroll
            for (int nj = 0; nj < 8; nj++) {
                const int c0 = n0 + wn + nj * 8 + 2 * tg;
                const size_t a0 = base + (size_t)c0 * (IMG * IMG);
                const size_t a1 = a0 + (IMG * IMG);
                out[a0] = acc[mi][nj][half * 2 + 0] + bo[c0]     + x[a0];
                out[a1] = acc[mi][nj][half * 2 + 1] + bo[c0 + 1] + x[a1];
            }
        }
    }
}

// ---------------------------------------------------------------------------
extern "C" void kernel_launch(void* const* d_in, const int* in_sizes, int n_in,
                              void* d_out, int out_size)
{
    const float* x    = (const float*)d_in[0];
    const float* gnw  = (const float*)d_in[1];
    const float* gnb  = (const float*)d_in[2];
    const float* Wq   = (const float*)d_in[3];
    const float* Wk   = (const float*)d_in[4];
    const float* Wv   = (const float*)d_in[5];
    const float* Wo   = (const float*)d_in[6];
    const float* bo   = (const float*)d_in[7];
    const float* pos  = (const float*)d_in[8];
    const float* scl  = (const float*)d_in[9];
    float* out = (float*)d_out;

    cudaFuncSetAttribute(qkv_gemm_kernel,     cudaFuncAttributeMaxDynamicSharedMemorySize, GM_SMEM);
    cudaFuncSetAttribute(outproj_gemm_kernel, cudaFuncAttributeMaxDynamicSharedMemorySize, GM_SMEM);
    cudaFuncSetAttribute(attn_kernel,         cudaFuncAttributeMaxDynamicSharedMemorySize, AT_SMEM);

    gn_stats_kernel<<<BATCH * 32, 512>>>(x);
    prep_w_kernel<<<512, 256>>>(Wq, Wk, Wv, Wo);
    prep_x_kernel<<<NTOK / 128, 256>>>(x, gnw, gnb);
    qkv_gemm_kernel<<<dim3(6, NTOK / 128), 256, GM_SMEM>>>(scl);
    attn_kernel<<<NTOK / NT, 256, AT_SMEM>>>(pos);
    outproj_gemm_kernel<<<dim3(2, NTOK / 128), 256, GM_SMEM>>>(x, bo, out);
}